// round 1
// baseline (speedup 1.0000x reference)
#include <cuda_runtime.h>
#include <cuda_bf16.h>
#include <cstdint>

// Problem constants
#define B_  4
#define T_  8
#define L_  512
#define D_  512
#define H_  8
#define KD_ 64
#define VD_ 64
#define BT_ 32            // B_*T_
#define M_TOT 16384       // BT_*L_
#define NDIM 512          // H_*KD_
#define KDIM 512          // D_

// Scratch: Q/K/V projections in (bt, h, l, e) layout, fp32
__device__ float g_Q[BT_ * H_ * L_ * KD_];
__device__ float g_K[BT_ * H_ * L_ * KD_];
__device__ float g_V[BT_ * H_ * L_ * VD_];

// ---------------------------------------------------------------------------
// Projection GEMM: C[m,n] = sum_k X[m,k] * W[k,n], M=16384, N=512, K=512
// X row-major (btl, d); W row-major (d, h*64+e).
// Output written to scratch with (bt, h, l, e) remap.
// 128x128 block tile, BK=16, 8x8 per thread, 256 threads.
// ---------------------------------------------------------------------------
__global__ __launch_bounds__(256)
void proj_gemm(const float* __restrict__ X, const float* __restrict__ W,
               float* __restrict__ out) {
    __shared__ float As[16][132];   // As[k][m] (transposed A tile)
    __shared__ float Bs[16][132];   // Bs[k][n]

    const int tid = threadIdx.x;
    const int bm = blockIdx.y * 128;
    const int bn = blockIdx.x * 128;
    const int tx = tid & 15;
    const int ty = tid >> 4;

    float acc[8][8];
#pragma unroll
    for (int i = 0; i < 8; i++)
#pragma unroll
        for (int j = 0; j < 8; j++) acc[i][j] = 0.f;

    const int ar_ = tid >> 1;         // 0..127  (A row within tile)
    const int ac_ = (tid & 1) * 8;    // 0 or 8  (A col start)
    const int br_ = tid >> 4;         // 0..15   (B row within k-tile)
    const int bc_ = (tid & 15) * 8;   // 0..120  (B col start)

    for (int k0 = 0; k0 < KDIM; k0 += 16) {
        float4 a0 = *(const float4*)(X + (size_t)(bm + ar_) * KDIM + k0 + ac_);
        float4 a1 = *(const float4*)(X + (size_t)(bm + ar_) * KDIM + k0 + ac_ + 4);
        float4 b0 = *(const float4*)(W + (size_t)(k0 + br_) * NDIM + bn + bc_);
        float4 b1 = *(const float4*)(W + (size_t)(k0 + br_) * NDIM + bn + bc_ + 4);

        As[ac_ + 0][ar_] = a0.x; As[ac_ + 1][ar_] = a0.y;
        As[ac_ + 2][ar_] = a0.z; As[ac_ + 3][ar_] = a0.w;
        As[ac_ + 4][ar_] = a1.x; As[ac_ + 5][ar_] = a1.y;
        As[ac_ + 6][ar_] = a1.z; As[ac_ + 7][ar_] = a1.w;

        *(float4*)&Bs[br_][bc_]     = b0;
        *(float4*)&Bs[br_][bc_ + 4] = b1;

        __syncthreads();

#pragma unroll
        for (int kk = 0; kk < 16; kk++) {
            float ar[8], br[8];
#pragma unroll
            for (int i = 0; i < 8; i++) ar[i] = As[kk][ty * 8 + i];
#pragma unroll
            for (int j = 0; j < 8; j++) br[j] = Bs[kk][tx * 8 + j];
#pragma unroll
            for (int i = 0; i < 8; i++)
#pragma unroll
                for (int j = 0; j < 8; j++)
                    acc[i][j] = fmaf(ar[i], br[j], acc[i][j]);
        }
        __syncthreads();
    }

    // Write with (bt, h, l, e) remap
#pragma unroll
    for (int i = 0; i < 8; i++) {
        const int m  = bm + ty * 8 + i;
        const int bt = m >> 9;
        const int l  = m & 511;
#pragma unroll
        for (int j = 0; j < 8; j++) {
            const int n = bn + tx * 8 + j;
            const int h = n >> 6;
            const int e = n & 63;
            out[(((size_t)(bt << 3) + h) * L_ + l) * 64 + e] = acc[i][j];
        }
    }
}

// ---------------------------------------------------------------------------
// Flash attention + head-weighted combine.
// One block = one (bt, 64-q-row tile). Loops over all 8 heads, streaming over
// 8 key chunks of 64 with online softmax. Accumulates sum_h w_h * attn_h into
// registers; single write of the final (l, e) tile.
// 256 threads: tx = tid&15 (4 e-cols each), ty = tid>>4 (4 q-rows each).
// ---------------------------------------------------------------------------
#define PAD 68
#define TILE_F (64 * PAD)
#define SMEM_ATTN ((4 * TILE_F + 3 * 64) * 4)

__global__ __launch_bounds__(256)
void attn_kernel(const float* __restrict__ Qg, const float* __restrict__ Kg,
                 const float* __restrict__ Vg, const float* __restrict__ mask,
                 const float* __restrict__ w_head, const float* __restrict__ tau,
                 const float* __restrict__ delta, float* __restrict__ out) {
    extern __shared__ float sm[];
    float (*Qt)[PAD] = (float(*)[PAD])(sm);
    float (*Kt)[PAD] = (float(*)[PAD])(sm + TILE_F);
    float (*Vt)[PAD] = (float(*)[PAD])(sm + 2 * TILE_F);
    float (*S)[PAD]  = (float(*)[PAD])(sm + 3 * TILE_F);
    float* rowm = sm + 4 * TILE_F;
    float* rowl = rowm + 64;
    float* rowa = rowl + 64;

    const int tid = threadIdx.x;
    const int tx = tid & 15;
    const int ty = tid >> 4;
    const int bt = blockIdx.y;
    const int r0 = blockIdx.x * 64;

    const float scale = 0.125f;              // 1/sqrt(64)
    const float t1 = tau[0] * scale;
    const float t2 = delta[0] * scale;

    const int ldr = tid >> 2;                // 0..63
    const int ldc = (tid & 3) * 16;          // 0,16,32,48

    float outAcc[4][4];
#pragma unroll
    for (int i = 0; i < 4; i++)
#pragma unroll
        for (int j = 0; j < 4; j++) outAcc[i][j] = 0.f;

    for (int h = 0; h < H_; h++) {
        const float wh = w_head[h];
        const size_t headBase = ((size_t)(bt * H_ + h)) * L_ * 64;

        // Load Q tile (64 x 64)
        const float* Qp = Qg + headBase + (size_t)r0 * 64;
#pragma unroll
        for (int u = 0; u < 4; u++)
            *(float4*)&Qt[ldr][ldc + u * 4] =
                *(const float4*)(Qp + (size_t)ldr * 64 + ldc + u * 4);

        if (tid < 64) { rowm[tid] = -3.0e38f; rowl[tid] = 0.f; }

        float Oa[4][4];
#pragma unroll
        for (int i = 0; i < 4; i++)
#pragma unroll
            for (int j = 0; j < 4; j++) Oa[i][j] = 0.f;

        for (int kc = 0; kc < 8; kc++) {
            const float* Kp = Kg + headBase + (size_t)(kc * 64) * 64;
            const float* Vp = Vg + headBase + (size_t)(kc * 64) * 64;
#pragma unroll
            for (int u = 0; u < 4; u++) {
                *(float4*)&Kt[ldr][ldc + u * 4] =
                    *(const float4*)(Kp + (size_t)ldr * 64 + ldc + u * 4);
                *(float4*)&Vt[ldr][ldc + u * 4] =
                    *(const float4*)(Vp + (size_t)ldr * 64 + ldc + u * 4);
            }
            __syncthreads();

            // S = Q * K^T for this 64x64 chunk
            float acc[4][4];
#pragma unroll
            for (int i = 0; i < 4; i++)
#pragma unroll
                for (int j = 0; j < 4; j++) acc[i][j] = 0.f;

#pragma unroll 4
            for (int k = 0; k < 64; k++) {
                float qa[4], kb[4];
#pragma unroll
                for (int i = 0; i < 4; i++) qa[i] = Qt[ty * 4 + i][k];
#pragma unroll
                for (int j = 0; j < 4; j++) kb[j] = Kt[tx * 4 + j][k];
#pragma unroll
                for (int i = 0; i < 4; i++)
#pragma unroll
                    for (int j = 0; j < 4; j++)
                        acc[i][j] = fmaf(qa[i], kb[j], acc[i][j]);
            }

            // Scale, shift, mask; store to smem S
#pragma unroll
            for (int i = 0; i < 4; i++) {
                const int row = ty * 4 + i;
                const float* mrow = mask + (size_t)(r0 + row) * L_ + kc * 64;
#pragma unroll
                for (int j = 0; j < 4; j++) {
                    const int col = tx * 4 + j;
                    S[row][col] = fmaf(acc[i][j], t1, t2) * mrow[col];
                }
            }
            __syncthreads();

            // Online softmax per row (64 owner threads)
            if (tid < 64) {
                const int r = tid;
                const float mold = rowm[r];
                float mx = mold;
#pragma unroll 8
                for (int c = 0; c < 64; c++) mx = fmaxf(mx, S[r][c]);
                const float a = __expf(mold - mx);
                float sum = 0.f;
#pragma unroll 8
                for (int c = 0; c < 64; c++) {
                    const float p = __expf(S[r][c] - mx);
                    S[r][c] = p;
                    sum += p;
                }
                rowl[r] = rowl[r] * a + sum;
                rowm[r] = mx;
                rowa[r] = a;
            }
            __syncthreads();

            // O = O*alpha + P*V
            float al[4];
#pragma unroll
            for (int i = 0; i < 4; i++) al[i] = rowa[ty * 4 + i];
#pragma unroll
            for (int i = 0; i < 4; i++)
#pragma unroll
                for (int j = 0; j < 4; j++) Oa[i][j] *= al[i];

#pragma unroll 4
            for (int k = 0; k < 64; k++) {
                float p[4], vv[4];
#pragma unroll
                for (int i = 0; i < 4; i++) p[i] = S[ty * 4 + i][k];
#pragma unroll
                for (int j = 0; j < 4; j++) vv[j] = Vt[k][tx * 4 + j];
#pragma unroll
                for (int i = 0; i < 4; i++)
#pragma unroll
                    for (int j = 0; j < 4; j++)
                        Oa[i][j] = fmaf(p[i], vv[j], Oa[i][j]);
            }
            __syncthreads();   // protect Kt/Vt/S before next chunk overwrites
        }

        // Finalize head: outAcc += w_h * O / l
        float il[4];
#pragma unroll
        for (int i = 0; i < 4; i++) il[i] = wh / rowl[ty * 4 + i];
#pragma unroll
        for (int i = 0; i < 4; i++)
#pragma unroll
            for (int j = 0; j < 4; j++)
                outAcc[i][j] = fmaf(Oa[i][j], il[i], outAcc[i][j]);

        __syncthreads();   // protect rowl/Qt before next head re-inits/reloads
    }

    // Write output tile (bt, l, e)
#pragma unroll
    for (int i = 0; i < 4; i++) {
        const int l = r0 + ty * 4 + i;
        float4 v;
        v.x = outAcc[i][0]; v.y = outAcc[i][1];
        v.z = outAcc[i][2]; v.w = outAcc[i][3];
        *(float4*)&out[((size_t)bt * L_ + l) * 64 + tx * 4] = v;
    }
}

// ---------------------------------------------------------------------------
extern "C" void kernel_launch(void* const* d_in, const int* in_sizes, int n_in,
                              void* d_out, int out_size) {
    const float* queries = (const float*)d_in[0];
    const float* keys    = (const float*)d_in[1];
    const float* values  = (const float*)d_in[2];
    const float* mask    = (const float*)d_in[3];
    const float* Wq      = (const float*)d_in[4];
    const float* Wk      = (const float*)d_in[5];
    const float* Wv      = (const float*)d_in[6];
    const float* w_head  = (const float*)d_in[7];
    const float* tau     = (const float*)d_in[8];
    const float* delta   = (const float*)d_in[9];
    float* out = (float*)d_out;

    float* qs; float* ks; float* vs;
    cudaGetSymbolAddress((void**)&qs, g_Q);
    cudaGetSymbolAddress((void**)&ks, g_K);
    cudaGetSymbolAddress((void**)&vs, g_V);

    dim3 gp(NDIM / 128, M_TOT / 128);   // (4, 128)
    proj_gemm<<<gp, 256>>>(queries, Wq, qs);
    proj_gemm<<<gp, 256>>>(keys,    Wk, ks);
    proj_gemm<<<gp, 256>>>(values,  Wv, vs);

    cudaFuncSetAttribute(attn_kernel,
                         cudaFuncAttributeMaxDynamicSharedMemorySize, SMEM_ATTN);
    dim3 ga(L_ / 64, BT_);              // (8, 32)
    attn_kernel<<<ga, 256, SMEM_ATTN>>>(qs, ks, vs, mask, w_head, tau, delta, out);
}

// round 2
// speedup vs baseline: 2.5737x; 2.5737x over previous
#include <cuda_runtime.h>
#include <cuda_bf16.h>
#include <cstdint>

// Problem constants
#define B_  4
#define T_  8
#define L_  512
#define D_  512
#define H_  8
#define BT_ 32            // B_*T_
#define M_TOT 16384       // BT_*L_
#define NDIM 512          // H_*64
#define KDIM 512          // D_

// Scratch (device globals: allocation-guard safe)
__device__ float g_Q[BT_ * H_ * L_ * 64];
__device__ float g_K[BT_ * H_ * L_ * 64];
__device__ float g_V[BT_ * H_ * L_ * 64];
__device__ float g_O[BT_ * H_ * L_ * 64];   // per-head weighted attention out

// ---------------------------------------------------------------------------
// helpers
// ---------------------------------------------------------------------------
__device__ __forceinline__ uint32_t f2tf32(float f) {
    uint32_t u;
    asm("cvt.rna.tf32.f32 %0, %1;" : "=r"(u) : "f"(f));
    return u;
}

__device__ __forceinline__ void mma_tf32(float c[4],
                                         uint32_t a0, uint32_t a1,
                                         uint32_t a2, uint32_t a3,
                                         uint32_t b0, uint32_t b1) {
    asm volatile(
        "mma.sync.aligned.m16n8k8.row.col.f32.tf32.tf32.f32 "
        "{%0,%1,%2,%3}, {%4,%5,%6,%7}, {%8,%9}, {%0,%1,%2,%3};\n"
        : "+f"(c[0]), "+f"(c[1]), "+f"(c[2]), "+f"(c[3])
        : "r"(a0), "r"(a1), "r"(a2), "r"(a3), "r"(b0), "r"(b1));
}

// ---------------------------------------------------------------------------
// Projection GEMM (TF32 tensor cores):
// C[m,n] = sum_k X[m,k]*W[k,n], M=16384, N=512, K=512.
// Block 128x128, k-chunk 16, 8 warps; warp tile 64(M)x32(N).
// Output remapped to (bt,h,l,e).
// ---------------------------------------------------------------------------
#define PSTR 136   // smem stride (136 % 32 == 8 -> conflict-free frag loads)

__global__ __launch_bounds__(256)
void proj_gemm_tf32(const float* __restrict__ X, const float* __restrict__ W,
                    float* __restrict__ out) {
    __shared__ uint32_t As[16][PSTR];   // [k][m] tf32
    __shared__ uint32_t Bs[16][PSTR];   // [k][n] tf32

    const int tid  = threadIdx.x;
    const int warp = tid >> 5;
    const int lane = tid & 31;
    const int g    = lane >> 2;     // groupID
    const int tg   = lane & 3;      // threadID_in_group

    const int bm = blockIdx.y * 128;
    const int bn = blockIdx.x * 128;
    const int wm = (warp & 1) * 64;      // M offset of warp tile
    const int wn = (warp >> 1) * 32;     // N offset of warp tile

    float acc[4][4][4];
#pragma unroll
    for (int i = 0; i < 4; i++)
#pragma unroll
        for (int j = 0; j < 4; j++)
#pragma unroll
            for (int r = 0; r < 4; r++) acc[i][j][r] = 0.f;

    const int ar_ = tid >> 1;          // A: m row within tile (0..127)
    const int ac_ = (tid & 1) * 8;     // A: k col start (0 or 8)
    const int br_ = tid >> 4;          // B: k row (0..15)
    const int bc_ = (tid & 15) * 8;    // B: n col start

    for (int k0 = 0; k0 < KDIM; k0 += 16) {
        // X -> As (transposed, tf32)
        float4 a0 = *(const float4*)(X + (size_t)(bm + ar_) * KDIM + k0 + ac_);
        float4 a1 = *(const float4*)(X + (size_t)(bm + ar_) * KDIM + k0 + ac_ + 4);
        As[ac_ + 0][ar_] = f2tf32(a0.x); As[ac_ + 1][ar_] = f2tf32(a0.y);
        As[ac_ + 2][ar_] = f2tf32(a0.z); As[ac_ + 3][ar_] = f2tf32(a0.w);
        As[ac_ + 4][ar_] = f2tf32(a1.x); As[ac_ + 5][ar_] = f2tf32(a1.y);
        As[ac_ + 6][ar_] = f2tf32(a1.z); As[ac_ + 7][ar_] = f2tf32(a1.w);
        // W -> Bs (direct, tf32)
        float4 b0 = *(const float4*)(W + (size_t)(k0 + br_) * NDIM + bn + bc_);
        float4 b1 = *(const float4*)(W + (size_t)(k0 + br_) * NDIM + bn + bc_ + 4);
        Bs[br_][bc_ + 0] = f2tf32(b0.x); Bs[br_][bc_ + 1] = f2tf32(b0.y);
        Bs[br_][bc_ + 2] = f2tf32(b0.z); Bs[br_][bc_ + 3] = f2tf32(b0.w);
        Bs[br_][bc_ + 4] = f2tf32(b1.x); Bs[br_][bc_ + 5] = f2tf32(b1.y);
        Bs[br_][bc_ + 6] = f2tf32(b1.z); Bs[br_][bc_ + 7] = f2tf32(b1.w);

        __syncthreads();

#pragma unroll
        for (int ks = 0; ks < 2; ks++) {
            uint32_t afr[4][4];
#pragma unroll
            for (int mf = 0; mf < 4; mf++) {
                const int mb = wm + mf * 16;
                afr[mf][0] = As[ks * 8 + tg][mb + g];
                afr[mf][1] = As[ks * 8 + tg][mb + g + 8];
                afr[mf][2] = As[ks * 8 + tg + 4][mb + g];
                afr[mf][3] = As[ks * 8 + tg + 4][mb + g + 8];
            }
            uint32_t bfr[4][2];
#pragma unroll
            for (int nf = 0; nf < 4; nf++) {
                const int nb = wn + nf * 8;
                bfr[nf][0] = Bs[ks * 8 + tg][nb + g];
                bfr[nf][1] = Bs[ks * 8 + tg + 4][nb + g];
            }
#pragma unroll
            for (int mf = 0; mf < 4; mf++)
#pragma unroll
                for (int nf = 0; nf < 4; nf++)
                    mma_tf32(acc[mf][nf], afr[mf][0], afr[mf][1], afr[mf][2],
                             afr[mf][3], bfr[nf][0], bfr[nf][1]);
        }
        __syncthreads();
    }

    // Epilogue with (bt,h,l,e) remap
#pragma unroll
    for (int mf = 0; mf < 4; mf++) {
#pragma unroll
        for (int nf = 0; nf < 4; nf++) {
            const int n = bn + wn + nf * 8 + tg * 2;
            const int h = n >> 6, e = n & 63;
#pragma unroll
            for (int half = 0; half < 2; half++) {
                const int m  = bm + wm + mf * 16 + g + half * 8;
                const int bt = m >> 9, l = m & 511;
                float* p = out + (((size_t)(bt << 3) + h) * L_ + l) * 64 + e;
                p[0] = acc[mf][nf][half * 2 + 0];
                p[1] = acc[mf][nf][half * 2 + 1];
            }
        }
    }
}

// ---------------------------------------------------------------------------
// Flash attention (TF32 MMA), one block per (bt, h, 64 q-rows).
// 128 threads = 4 warps; warp w owns q-rows [16w, 16w+16).
// Q fragments live in registers for the whole block.
// ---------------------------------------------------------------------------
#define ASTR 68    // 68 % 32 == 4 -> conflict-free frag loads
#define ATTN_SMEM (3 * 64 * ASTR * 4)

__global__ __launch_bounds__(128)
void attn_tf32(const float* __restrict__ Qg, const float* __restrict__ Kg,
               const float* __restrict__ Vg, const float* __restrict__ mask,
               const float* __restrict__ w_head, const float* __restrict__ tau,
               const float* __restrict__ delta, float* __restrict__ Og) {
    extern __shared__ uint32_t smu[];
    uint32_t (*Ks)[ASTR] = (uint32_t(*)[ASTR])smu;               // K[s][e]
    uint32_t (*Vt)[ASTR] = (uint32_t(*)[ASTR])(smu + 64 * ASTR); // V^T[e][s]
    uint32_t (*Ps)[ASTR] = (uint32_t(*)[ASTR])(smu + 2 * 64 * ASTR); // Q then P

    const int tid  = threadIdx.x;
    const int warp = tid >> 5;
    const int lane = tid & 31;
    const int g    = lane >> 2;
    const int tg   = lane & 3;
    const int wrow = warp * 16;

    const int qt = blockIdx.x;        // q tile (0..7)
    const int h  = blockIdx.y;
    const int bt = blockIdx.z;
    const int r0 = qt * 64;

    const float scale = 0.125f;
    const float t1 = tau[0] * scale;
    const float t2 = delta[0] * scale;
    const float wh = w_head[h];

    const size_t headBase = ((size_t)(bt * H_ + h)) * L_ * 64;

    // ---- stage Q tile (scaled by t1, tf32) into Ps, then to registers ----
    const int lr = tid >> 1;                // 0..63
    const int lc = (tid & 1) * 32;          // 0 or 32
    {
        const float* Qp = Qg + headBase + (size_t)(r0 + lr) * 64 + lc;
#pragma unroll
        for (int u = 0; u < 8; u++) {
            float4 v = *(const float4*)(Qp + u * 4);
            Ps[lr][lc + u * 4 + 0] = f2tf32(v.x * t1);
            Ps[lr][lc + u * 4 + 1] = f2tf32(v.y * t1);
            Ps[lr][lc + u * 4 + 2] = f2tf32(v.z * t1);
            Ps[lr][lc + u * 4 + 3] = f2tf32(v.w * t1);
        }
    }
    __syncthreads();

    uint32_t qa[8][4];
#pragma unroll
    for (int ks = 0; ks < 8; ks++) {
        qa[ks][0] = Ps[wrow + g][ks * 8 + tg];
        qa[ks][1] = Ps[wrow + g + 8][ks * 8 + tg];
        qa[ks][2] = Ps[wrow + g][ks * 8 + tg + 4];
        qa[ks][3] = Ps[wrow + g + 8][ks * 8 + tg + 4];
    }

    // online softmax state (rows wrow+g and wrow+g+8)
    float m0 = -3.0e38f, m1 = -3.0e38f, l0 = 0.f, l1 = 0.f;
    float o[8][4];
#pragma unroll
    for (int nf = 0; nf < 8; nf++)
#pragma unroll
        for (int r = 0; r < 4; r++) o[nf][r] = 0.f;

    for (int kc = 0; kc < 8; kc++) {
        // ---- load K chunk [s][e] and V chunk transposed [e][s] ----
        const float* Kp = Kg + headBase + (size_t)(kc * 64 + lr) * 64 + lc;
        const float* Vp = Vg + headBase + (size_t)(kc * 64 + lr) * 64 + lc;
#pragma unroll
        for (int u = 0; u < 8; u++) {
            float4 kv = *(const float4*)(Kp + u * 4);
            Ks[lr][lc + u * 4 + 0] = f2tf32(kv.x);
            Ks[lr][lc + u * 4 + 1] = f2tf32(kv.y);
            Ks[lr][lc + u * 4 + 2] = f2tf32(kv.z);
            Ks[lr][lc + u * 4 + 3] = f2tf32(kv.w);
            float4 vv = *(const float4*)(Vp + u * 4);
            Vt[lc + u * 4 + 0][lr] = f2tf32(vv.x);
            Vt[lc + u * 4 + 1][lr] = f2tf32(vv.y);
            Vt[lc + u * 4 + 2][lr] = f2tf32(vv.z);
            Vt[lc + u * 4 + 3][lr] = f2tf32(vv.w);
        }
        __syncthreads();

        // ---- S = (Q*t1) K^T  (16x64 per warp) ----
        float s[8][4];
#pragma unroll
        for (int nf = 0; nf < 8; nf++)
#pragma unroll
            for (int r = 0; r < 4; r++) s[nf][r] = 0.f;

#pragma unroll
        for (int ks = 0; ks < 8; ks++) {
#pragma unroll
            for (int nf = 0; nf < 8; nf++) {
                uint32_t b0 = Ks[nf * 8 + g][ks * 8 + tg];
                uint32_t b1 = Ks[nf * 8 + g][ks * 8 + tg + 4];
                mma_tf32(s[nf], qa[ks][0], qa[ks][1], qa[ks][2], qa[ks][3],
                         b0, b1);
            }
        }

        // ---- epilogue: +t2, *mask ----
        const int rlo = r0 + wrow + g;
#pragma unroll
        for (int nf = 0; nf < 8; nf++) {
            const int c0 = kc * 64 + nf * 8 + tg * 2;
            const float mk00 = mask[(size_t)rlo * L_ + c0];
            const float mk01 = mask[(size_t)rlo * L_ + c0 + 1];
            const float mk10 = mask[(size_t)(rlo + 8) * L_ + c0];
            const float mk11 = mask[(size_t)(rlo + 8) * L_ + c0 + 1];
            s[nf][0] = (s[nf][0] + t2) * mk00;
            s[nf][1] = (s[nf][1] + t2) * mk01;
            s[nf][2] = (s[nf][2] + t2) * mk10;
            s[nf][3] = (s[nf][3] + t2) * mk11;
        }

        // ---- online softmax (rows lo/hi per thread) ----
        float mx0 = -3.0e38f, mx1 = -3.0e38f;
#pragma unroll
        for (int nf = 0; nf < 8; nf++) {
            mx0 = fmaxf(mx0, fmaxf(s[nf][0], s[nf][1]));
            mx1 = fmaxf(mx1, fmaxf(s[nf][2], s[nf][3]));
        }
        mx0 = fmaxf(mx0, __shfl_xor_sync(0xffffffffu, mx0, 1));
        mx0 = fmaxf(mx0, __shfl_xor_sync(0xffffffffu, mx0, 2));
        mx1 = fmaxf(mx1, __shfl_xor_sync(0xffffffffu, mx1, 1));
        mx1 = fmaxf(mx1, __shfl_xor_sync(0xffffffffu, mx1, 2));

        const float mn0 = fmaxf(m0, mx0);
        const float mn1 = fmaxf(m1, mx1);
        const float al0 = __expf(m0 - mn0);
        const float al1 = __expf(m1 - mn1);

        float sum0 = 0.f, sum1 = 0.f;
#pragma unroll
        for (int nf = 0; nf < 8; nf++) {
            s[nf][0] = __expf(s[nf][0] - mn0);
            s[nf][1] = __expf(s[nf][1] - mn0);
            s[nf][2] = __expf(s[nf][2] - mn1);
            s[nf][3] = __expf(s[nf][3] - mn1);
            sum0 += s[nf][0] + s[nf][1];
            sum1 += s[nf][2] + s[nf][3];
        }
        sum0 += __shfl_xor_sync(0xffffffffu, sum0, 1);
        sum0 += __shfl_xor_sync(0xffffffffu, sum0, 2);
        sum1 += __shfl_xor_sync(0xffffffffu, sum1, 1);
        sum1 += __shfl_xor_sync(0xffffffffu, sum1, 2);

        l0 = l0 * al0 + sum0;  m0 = mn0;
        l1 = l1 * al1 + sum1;  m1 = mn1;

        // rescale O
#pragma unroll
        for (int nf = 0; nf < 8; nf++) {
            o[nf][0] *= al0; o[nf][1] *= al0;
            o[nf][2] *= al1; o[nf][3] *= al1;
        }

        // ---- P -> smem (tf32); own rows only, no barrier needed ----
#pragma unroll
        for (int nf = 0; nf < 8; nf++) {
            const int c = nf * 8 + tg * 2;
            Ps[wrow + g][c]         = f2tf32(s[nf][0]);
            Ps[wrow + g][c + 1]     = f2tf32(s[nf][1]);
            Ps[wrow + g + 8][c]     = f2tf32(s[nf][2]);
            Ps[wrow + g + 8][c + 1] = f2tf32(s[nf][3]);
        }

        // ---- O += P V  (A = P own rows from Ps, B = Vt) ----
#pragma unroll
        for (int ks = 0; ks < 8; ks++) {
            uint32_t pa0 = Ps[wrow + g][ks * 8 + tg];
            uint32_t pa1 = Ps[wrow + g + 8][ks * 8 + tg];
            uint32_t pa2 = Ps[wrow + g][ks * 8 + tg + 4];
            uint32_t pa3 = Ps[wrow + g + 8][ks * 8 + tg + 4];
#pragma unroll
            for (int nf = 0; nf < 8; nf++) {
                uint32_t b0 = Vt[nf * 8 + g][ks * 8 + tg];
                uint32_t b1 = Vt[nf * 8 + g][ks * 8 + tg + 4];
                mma_tf32(o[nf], pa0, pa1, pa2, pa3, b0, b1);
            }
        }
        __syncthreads();   // Ks/Vt/Ps consumed before next chunk overwrites
    }

    // ---- finalize: *(wh/l), write (bt,h,l,e) ----
    const float i0 = wh / l0;
    const float i1 = wh / l1;
    const int rlo = r0 + wrow + g;
    float* obase = Og + headBase;
#pragma unroll
    for (int nf = 0; nf < 8; nf++) {
        const int e = nf * 8 + tg * 2;
        float2 v0 = make_float2(o[nf][0] * i0, o[nf][1] * i0);
        float2 v1 = make_float2(o[nf][2] * i1, o[nf][3] * i1);
        *(float2*)(obase + (size_t)rlo * 64 + e)       = v0;
        *(float2*)(obase + (size_t)(rlo + 8) * 64 + e) = v1;
    }
}

// ---------------------------------------------------------------------------
// Head combine: out[bt,l,e] = sum_h O[bt,h,l,e]   (w_h already folded in)
// ---------------------------------------------------------------------------
__global__ __launch_bounds__(256)
void combine_heads(const float* __restrict__ O, float* __restrict__ out) {
    const int idx = blockIdx.x * 256 + threadIdx.x;   // over 262144 float4
    const int btl = idx >> 4;
    const int e   = (idx & 15) * 4;
    const int bt  = btl >> 9;
    const int l   = btl & 511;

    float4 acc = make_float4(0.f, 0.f, 0.f, 0.f);
#pragma unroll
    for (int h = 0; h < H_; h++) {
        const float4 v = *(const float4*)(O +
            (((size_t)(bt * H_ + h)) * L_ + l) * 64 + e);
        acc.x += v.x; acc.y += v.y; acc.z += v.z; acc.w += v.w;
    }
    *(float4*)(out + (size_t)btl * 64 + e) = acc;
}

// ---------------------------------------------------------------------------
extern "C" void kernel_launch(void* const* d_in, const int* in_sizes, int n_in,
                              void* d_out, int out_size) {
    const float* queries = (const float*)d_in[0];
    const float* keys    = (const float*)d_in[1];
    const float* values  = (const float*)d_in[2];
    const float* mask    = (const float*)d_in[3];
    const float* Wq      = (const float*)d_in[4];
    const float* Wk      = (const float*)d_in[5];
    const float* Wv      = (const float*)d_in[6];
    const float* w_head  = (const float*)d_in[7];
    const float* tau     = (const float*)d_in[8];
    const float* delta   = (const float*)d_in[9];
    float* out = (float*)d_out;

    float *qs, *ks, *vs, *os;
    cudaGetSymbolAddress((void**)&qs, g_Q);
    cudaGetSymbolAddress((void**)&ks, g_K);
    cudaGetSymbolAddress((void**)&vs, g_V);
    cudaGetSymbolAddress((void**)&os, g_O);

    dim3 gp(NDIM / 128, M_TOT / 128);   // (4, 128)
    proj_gemm_tf32<<<gp, 256>>>(queries, Wq, qs);
    proj_gemm_tf32<<<gp, 256>>>(keys,    Wk, ks);
    proj_gemm_tf32<<<gp, 256>>>(values,  Wv, vs);

    static int smset = 0;
    if (!smset) {
        cudaFuncSetAttribute(attn_tf32,
                             cudaFuncAttributeMaxDynamicSharedMemorySize,
                             ATTN_SMEM);
        smset = 1;
    }
    dim3 ga(L_ / 64, H_, BT_);          // (8, 8, 32)
    attn_tf32<<<ga, 128, ATTN_SMEM>>>(qs, ks, vs, mask, w_head, tau, delta, os);

    combine_heads<<<1024, 256>>>(os, out);
}

// round 3
// speedup vs baseline: 2.6949x; 1.0471x over previous
#include <cuda_runtime.h>
#include <cuda_bf16.h>
#include <cstdint>

// Problem constants
#define B_  4
#define T_  8
#define L_  512
#define D_  512
#define H_  8
#define BT_ 32            // B_*T_
#define M_TOT 16384       // BT_*L_
#define NDIM 512          // H_*64
#define KDIM 512          // D_

// Scratch (device globals: allocation-guard safe)
__device__ float g_Q[BT_ * H_ * L_ * 64];
__device__ float g_K[BT_ * H_ * L_ * 64];
__device__ float g_V[BT_ * H_ * L_ * 64];
__device__ float g_O[BT_ * H_ * L_ * 64];   // per-head weighted attention out

// ---------------------------------------------------------------------------
// helpers
// ---------------------------------------------------------------------------
__device__ __forceinline__ uint32_t f2tf32(float f) {
    uint32_t u;
    asm("cvt.rna.tf32.f32 %0, %1;" : "=r"(u) : "f"(f));
    return u;
}

__device__ __forceinline__ uint4 cvt4(float4 v) {
    uint4 r;
    r.x = f2tf32(v.x); r.y = f2tf32(v.y);
    r.z = f2tf32(v.z); r.w = f2tf32(v.w);
    return r;
}

__device__ __forceinline__ void mma_tf32(float c[4],
                                         uint32_t a0, uint32_t a1,
                                         uint32_t a2, uint32_t a3,
                                         uint32_t b0, uint32_t b1) {
    asm volatile(
        "mma.sync.aligned.m16n8k8.row.col.f32.tf32.tf32.f32 "
        "{%0,%1,%2,%3}, {%4,%5,%6,%7}, {%8,%9}, {%0,%1,%2,%3};\n"
        : "+f"(c[0]), "+f"(c[1]), "+f"(c[2]), "+f"(c[3])
        : "r"(a0), "r"(a1), "r"(a2), "r"(a3), "r"(b0), "r"(b1));
}

// ---------------------------------------------------------------------------
// Fused projection GEMMs (TF32), all three in one launch (blockIdx.z picks).
// C[m,n] = sum_k X[m,k]*W[k,n], M=16384, N=512, K=512.
// Block 128x128, k-chunk 32, 8 warps; warp tile 64(M)x32(N).
// A kept row-major in smem (STS.128 staging, conflict-free frag loads at
// stride 36); B [k][n] stride 136. Output remapped to (bt,h,l,e).
// ---------------------------------------------------------------------------
__global__ __launch_bounds__(256)
void proj3_tf32(const float* __restrict__ Xq, const float* __restrict__ Xk,
                const float* __restrict__ Xv, const float* __restrict__ Wq,
                const float* __restrict__ Wk, const float* __restrict__ Wv,
                float* __restrict__ Oq, float* __restrict__ Ok,
                float* __restrict__ Ov) {
    __shared__ uint32_t As[128][36];   // [m][k] row-major tf32, stride 36
    __shared__ uint32_t Bs[32][136];   // [k][n] tf32, stride 136

    const int z = blockIdx.z;
    const float* X = (z == 0) ? Xq : (z == 1) ? Xk : Xv;
    const float* W = (z == 0) ? Wq : (z == 1) ? Wk : Wv;
    float* out     = (z == 0) ? Oq : (z == 1) ? Ok : Ov;

    const int tid  = threadIdx.x;
    const int warp = tid >> 5;
    const int lane = tid & 31;
    const int g    = lane >> 2;
    const int tg   = lane & 3;

    const int bm = blockIdx.y * 128;
    const int bn = blockIdx.x * 128;
    const int wm = (warp & 1) * 64;
    const int wn = (warp >> 1) * 32;

    float acc[4][4][4];
#pragma unroll
    for (int i = 0; i < 4; i++)
#pragma unroll
        for (int j = 0; j < 4; j++)
#pragma unroll
            for (int r = 0; r < 4; r++) acc[i][j][r] = 0.f;

    const int arow = tid >> 1;           // 0..127
    const int acol = (tid & 1) * 16;     // 0 or 16
    const int brow = tid >> 3;           // 0..31
    const int bcol = (tid & 7) * 16;     // 0..112

    for (int k0 = 0; k0 < KDIM; k0 += 32) {
        // A tile 128x32, row-major
#pragma unroll
        for (int u = 0; u < 4; u++) {
            float4 v = *(const float4*)(X + (size_t)(bm + arow) * KDIM +
                                        k0 + acol + u * 4);
            *(uint4*)&As[arow][acol + u * 4] = cvt4(v);
        }
        // B tile 32x128
#pragma unroll
        for (int u = 0; u < 4; u++) {
            float4 v = *(const float4*)(W + (size_t)(k0 + brow) * NDIM +
                                        bn + bcol + u * 4);
            *(uint4*)&Bs[brow][bcol + u * 4] = cvt4(v);
        }
        __syncthreads();

#pragma unroll
        for (int ks = 0; ks < 4; ks++) {
            uint32_t afr[4][4];
#pragma unroll
            for (int mf = 0; mf < 4; mf++) {
                const int mb = wm + mf * 16;
                afr[mf][0] = As[mb + g][ks * 8 + tg];
                afr[mf][1] = As[mb + g + 8][ks * 8 + tg];
                afr[mf][2] = As[mb + g][ks * 8 + tg + 4];
                afr[mf][3] = As[mb + g + 8][ks * 8 + tg + 4];
            }
            uint32_t bfr[4][2];
#pragma unroll
            for (int nf = 0; nf < 4; nf++) {
                const int nb = wn + nf * 8;
                bfr[nf][0] = Bs[ks * 8 + tg][nb + g];
                bfr[nf][1] = Bs[ks * 8 + tg + 4][nb + g];
            }
#pragma unroll
            for (int mf = 0; mf < 4; mf++)
#pragma unroll
                for (int nf = 0; nf < 4; nf++)
                    mma_tf32(acc[mf][nf], afr[mf][0], afr[mf][1], afr[mf][2],
                             afr[mf][3], bfr[nf][0], bfr[nf][1]);
        }
        __syncthreads();
    }

    // Epilogue with (bt,h,l,e) remap
#pragma unroll
    for (int mf = 0; mf < 4; mf++) {
#pragma unroll
        for (int nf = 0; nf < 4; nf++) {
            const int n = bn + wn + nf * 8 + tg * 2;
            const int h = n >> 6, e = n & 63;
#pragma unroll
            for (int half = 0; half < 2; half++) {
                const int m  = bm + wm + mf * 16 + g + half * 8;
                const int bt = m >> 9, l = m & 511;
                float* p = out + (((size_t)(bt << 3) + h) * L_ + l) * 64 + e;
                p[0] = acc[mf][nf][half * 2 + 0];
                p[1] = acc[mf][nf][half * 2 + 1];
            }
        }
    }
}

// ---------------------------------------------------------------------------
// Flash attention (TF32 MMA), one block per (bt, h, 64 q-rows).
// 128 threads = 4 warps; warp w owns q-rows [16w, 16w+16).
// K and V staged in NATURAL [s][e] layout (mma row.col B-frags match both);
// Vs uses stride 72 (8 mod 32) for conflict-free PV B-frag loads, Ks/Ps use
// stride 68 (4 mod 32) for conflict-free QK/P frag loads. All staging stores
// vectorized (STS.128 / STS.64).
// ---------------------------------------------------------------------------
#define KS_STR 68
#define VS_STR 72
#define PS_STR 68
#define ATTN_SMEM (64 * (KS_STR + VS_STR + PS_STR) * 4)

__global__ __launch_bounds__(128)
void attn_tf32(const float* __restrict__ Qg, const float* __restrict__ Kg,
               const float* __restrict__ Vg, const float* __restrict__ mask,
               const float* __restrict__ w_head, const float* __restrict__ tau,
               const float* __restrict__ delta, float* __restrict__ Og) {
    extern __shared__ uint32_t smu[];
    uint32_t (*Ks)[KS_STR] = (uint32_t(*)[KS_STR])smu;                   // K[s][e]
    uint32_t (*Vs)[VS_STR] = (uint32_t(*)[VS_STR])(smu + 64 * KS_STR);   // V[s][e]
    uint32_t (*Ps)[PS_STR] =
        (uint32_t(*)[PS_STR])(smu + 64 * (KS_STR + VS_STR));             // Q then P

    const int tid  = threadIdx.x;
    const int warp = tid >> 5;
    const int lane = tid & 31;
    const int g    = lane >> 2;
    const int tg   = lane & 3;
    const int wrow = warp * 16;

    const int qt = blockIdx.x;
    const int h  = blockIdx.y;
    const int bt = blockIdx.z;
    const int r0 = qt * 64;

    const float scale = 0.125f;
    const float t1 = tau[0] * scale;
    const float t2 = delta[0] * scale;
    const float wh = w_head[h];

    const size_t headBase = ((size_t)(bt * H_ + h)) * L_ * 64;

    const int lr = tid >> 1;                // 0..63
    const int lc = (tid & 1) * 32;          // 0 or 32

    // ---- stage Q tile (scaled by t1, tf32) into Ps ----
    {
        const float* Qp = Qg + headBase + (size_t)(r0 + lr) * 64 + lc;
#pragma unroll
        for (int u = 0; u < 8; u++) {
            float4 v = *(const float4*)(Qp + u * 4);
            v.x *= t1; v.y *= t1; v.z *= t1; v.w *= t1;
            *(uint4*)&Ps[lr][lc + u * 4] = cvt4(v);
        }
    }
    __syncthreads();

    uint32_t qa[8][4];
#pragma unroll
    for (int ks = 0; ks < 8; ks++) {
        qa[ks][0] = Ps[wrow + g][ks * 8 + tg];
        qa[ks][1] = Ps[wrow + g + 8][ks * 8 + tg];
        qa[ks][2] = Ps[wrow + g][ks * 8 + tg + 4];
        qa[ks][3] = Ps[wrow + g + 8][ks * 8 + tg + 4];
    }
    // Ps is only ever read/written by a warp on its OWN 16 rows after this,
    // but the Q-frag reads above must complete before Ps is reused for P.
    __syncthreads();

    float m0 = -3.0e38f, m1 = -3.0e38f, l0 = 0.f, l1 = 0.f;
    float o[8][4];
#pragma unroll
    for (int nf = 0; nf < 8; nf++)
#pragma unroll
        for (int r = 0; r < 4; r++) o[nf][r] = 0.f;

    for (int kc = 0; kc < 8; kc++) {
        // ---- stage K and V chunks (natural [s][e], tf32, STS.128) ----
        const float* Kp = Kg + headBase + (size_t)(kc * 64 + lr) * 64 + lc;
        const float* Vp = Vg + headBase + (size_t)(kc * 64 + lr) * 64 + lc;
#pragma unroll
        for (int u = 0; u < 8; u++) {
            *(uint4*)&Ks[lr][lc + u * 4] = cvt4(*(const float4*)(Kp + u * 4));
            *(uint4*)&Vs[lr][lc + u * 4] = cvt4(*(const float4*)(Vp + u * 4));
        }
        __syncthreads();

        // ---- S = (Q*t1) K^T  (16x64 per warp) ----
        float s[8][4];
#pragma unroll
        for (int nf = 0; nf < 8; nf++)
#pragma unroll
            for (int r = 0; r < 4; r++) s[nf][r] = 0.f;

#pragma unroll
        for (int ks = 0; ks < 8; ks++) {
#pragma unroll
            for (int nf = 0; nf < 8; nf++) {
                uint32_t b0 = Ks[nf * 8 + g][ks * 8 + tg];
                uint32_t b1 = Ks[nf * 8 + g][ks * 8 + tg + 4];
                mma_tf32(s[nf], qa[ks][0], qa[ks][1], qa[ks][2], qa[ks][3],
                         b0, b1);
            }
        }

        // ---- epilogue: +t2, *mask (float2 loads) ----
        const int rlo = r0 + wrow + g;
#pragma unroll
        for (int nf = 0; nf < 8; nf++) {
            const int c0 = kc * 64 + nf * 8 + tg * 2;
            const float2 mk0 = *(const float2*)(mask + (size_t)rlo * L_ + c0);
            const float2 mk1 =
                *(const float2*)(mask + (size_t)(rlo + 8) * L_ + c0);
            s[nf][0] = (s[nf][0] + t2) * mk0.x;
            s[nf][1] = (s[nf][1] + t2) * mk0.y;
            s[nf][2] = (s[nf][2] + t2) * mk1.x;
            s[nf][3] = (s[nf][3] + t2) * mk1.y;
        }

        // ---- online softmax ----
        float mx0 = -3.0e38f, mx1 = -3.0e38f;
#pragma unroll
        for (int nf = 0; nf < 8; nf++) {
            mx0 = fmaxf(mx0, fmaxf(s[nf][0], s[nf][1]));
            mx1 = fmaxf(mx1, fmaxf(s[nf][2], s[nf][3]));
        }
        mx0 = fmaxf(mx0, __shfl_xor_sync(0xffffffffu, mx0, 1));
        mx0 = fmaxf(mx0, __shfl_xor_sync(0xffffffffu, mx0, 2));
        mx1 = fmaxf(mx1, __shfl_xor_sync(0xffffffffu, mx1, 1));
        mx1 = fmaxf(mx1, __shfl_xor_sync(0xffffffffu, mx1, 2));

        const float mn0 = fmaxf(m0, mx0);
        const float mn1 = fmaxf(m1, mx1);
        const float al0 = __expf(m0 - mn0);
        const float al1 = __expf(m1 - mn1);

        float sum0 = 0.f, sum1 = 0.f;
#pragma unroll
        for (int nf = 0; nf < 8; nf++) {
            s[nf][0] = __expf(s[nf][0] - mn0);
            s[nf][1] = __expf(s[nf][1] - mn0);
            s[nf][2] = __expf(s[nf][2] - mn1);
            s[nf][3] = __expf(s[nf][3] - mn1);
            sum0 += s[nf][0] + s[nf][1];
            sum1 += s[nf][2] + s[nf][3];
        }
        sum0 += __shfl_xor_sync(0xffffffffu, sum0, 1);
        sum0 += __shfl_xor_sync(0xffffffffu, sum0, 2);
        sum1 += __shfl_xor_sync(0xffffffffu, sum1, 1);
        sum1 += __shfl_xor_sync(0xffffffffu, sum1, 2);

        l0 = l0 * al0 + sum0;  m0 = mn0;
        l1 = l1 * al1 + sum1;  m1 = mn1;

#pragma unroll
        for (int nf = 0; nf < 8; nf++) {
            o[nf][0] *= al0; o[nf][1] *= al0;
            o[nf][2] *= al1; o[nf][3] *= al1;
        }

        // ---- P -> smem (tf32, STS.64); own rows only, no barrier needed ----
#pragma unroll
        for (int nf = 0; nf < 8; nf++) {
            const int c = nf * 8 + tg * 2;
            uint2 plo, phi;
            plo.x = f2tf32(s[nf][0]); plo.y = f2tf32(s[nf][1]);
            phi.x = f2tf32(s[nf][2]); phi.y = f2tf32(s[nf][3]);
            *(uint2*)&Ps[wrow + g][c]     = plo;
            *(uint2*)&Ps[wrow + g + 8][c] = phi;
        }

        // ---- O += P V  (A = P own rows; B = V natural [s][e]) ----
#pragma unroll
        for (int ks = 0; ks < 8; ks++) {
            uint32_t pa0 = Ps[wrow + g][ks * 8 + tg];
            uint32_t pa1 = Ps[wrow + g + 8][ks * 8 + tg];
            uint32_t pa2 = Ps[wrow + g][ks * 8 + tg + 4];
            uint32_t pa3 = Ps[wrow + g + 8][ks * 8 + tg + 4];
#pragma unroll
            for (int nf = 0; nf < 8; nf++) {
                uint32_t b0 = Vs[ks * 8 + tg][nf * 8 + g];
                uint32_t b1 = Vs[ks * 8 + tg + 4][nf * 8 + g];
                mma_tf32(o[nf], pa0, pa1, pa2, pa3, b0, b1);
            }
        }
        __syncthreads();   // Ks/Vs consumed before next chunk overwrites
    }

    // ---- finalize: *(wh/l), write (bt,h,l,e) ----
    const float i0 = wh / l0;
    const float i1 = wh / l1;
    const int rlo = r0 + wrow + g;
    float* obase = Og + headBase;
#pragma unroll
    for (int nf = 0; nf < 8; nf++) {
        const int e = nf * 8 + tg * 2;
        float2 v0 = make_float2(o[nf][0] * i0, o[nf][1] * i0);
        float2 v1 = make_float2(o[nf][2] * i1, o[nf][3] * i1);
        *(float2*)(obase + (size_t)rlo * 64 + e)       = v0;
        *(float2*)(obase + (size_t)(rlo + 8) * 64 + e) = v1;
    }
}

// ---------------------------------------------------------------------------
// Head combine: out[bt,l,e] = sum_h O[bt,h,l,e]   (w_h already folded in)
// ---------------------------------------------------------------------------
__global__ __launch_bounds__(256)
void combine_heads(const float* __restrict__ O, float* __restrict__ out) {
    const int idx = blockIdx.x * 256 + threadIdx.x;
    const int btl = idx >> 4;
    const int e   = (idx & 15) * 4;
    const int bt  = btl >> 9;
    const int l   = btl & 511;

    float4 acc = make_float4(0.f, 0.f, 0.f, 0.f);
#pragma unroll
    for (int h = 0; h < H_; h++) {
        const float4 v = *(const float4*)(O +
            (((size_t)(bt * H_ + h)) * L_ + l) * 64 + e);
        acc.x += v.x; acc.y += v.y; acc.z += v.z; acc.w += v.w;
    }
    *(float4*)(out + (size_t)btl * 64 + e) = acc;
}

// ---------------------------------------------------------------------------
extern "C" void kernel_launch(void* const* d_in, const int* in_sizes, int n_in,
                              void* d_out, int out_size) {
    const float* queries = (const float*)d_in[0];
    const float* keys    = (const float*)d_in[1];
    const float* values  = (const float*)d_in[2];
    const float* mask    = (const float*)d_in[3];
    const float* Wq      = (const float*)d_in[4];
    const float* Wk      = (const float*)d_in[5];
    const float* Wv      = (const float*)d_in[6];
    const float* w_head  = (const float*)d_in[7];
    const float* tau     = (const float*)d_in[8];
    const float* delta   = (const float*)d_in[9];
    float* out = (float*)d_out;

    float *qs, *ks, *vs, *os;
    cudaGetSymbolAddress((void**)&qs, g_Q);
    cudaGetSymbolAddress((void**)&ks, g_K);
    cudaGetSymbolAddress((void**)&vs, g_V);
    cudaGetSymbolAddress((void**)&os, g_O);

    dim3 gp(NDIM / 128, M_TOT / 128, 3);   // (4, 128, 3) — fused Q/K/V proj
    proj3_tf32<<<gp, 256>>>(queries, keys, values, Wq, Wk, Wv, qs, ks, vs);

    cudaFuncSetAttribute(attn_tf32,
                         cudaFuncAttributeMaxDynamicSharedMemorySize,
                         ATTN_SMEM);
    dim3 ga(L_ / 64, H_, BT_);             // (8, 8, 32)
    attn_tf32<<<ga, 128, ATTN_SMEM>>>(qs, ks, vs, mask, w_head, tau, delta, os);

    combine_heads<<<1024, 256>>>(os, out);
}

// round 11
// speedup vs baseline: 2.7261x; 1.0116x over previous
#include <cuda_runtime.h>
#include <cuda_bf16.h>
#include <cstdint>

// Problem constants
#define B_  4
#define T_  8
#define L_  512
#define D_  512
#define H_  8
#define BT_ 32            // B_*T_
#define M_TOT 16384       // BT_*L_
#define NDIM 512          // H_*64
#define KDIM 512          // D_

// Scratch (device globals: allocation-guard safe)
__device__ float g_Q[BT_ * H_ * L_ * 64];
__device__ float g_K[BT_ * H_ * L_ * 64];
__device__ float g_V[BT_ * H_ * L_ * 64];
__device__ float g_O[BT_ * H_ * L_ * 64];   // per-head weighted attention out

// ---------------------------------------------------------------------------
// helpers
// ---------------------------------------------------------------------------
__device__ __forceinline__ uint32_t f2tf32(float f) {
    uint32_t u;
    asm("cvt.rna.tf32.f32 %0, %1;" : "=r"(u) : "f"(f));
    return u;
}

__device__ __forceinline__ uint4 cvt4(float4 v) {
    uint4 r;
    r.x = f2tf32(v.x); r.y = f2tf32(v.y);
    r.z = f2tf32(v.z); r.w = f2tf32(v.w);
    return r;
}

__device__ __forceinline__ void mma_tf32(float c[4],
                                         uint32_t a0, uint32_t a1,
                                         uint32_t a2, uint32_t a3,
                                         uint32_t b0, uint32_t b1) {
    asm volatile(
        "mma.sync.aligned.m16n8k8.row.col.f32.tf32.tf32.f32 "
        "{%0,%1,%2,%3}, {%4,%5,%6,%7}, {%8,%9}, {%0,%1,%2,%3};\n"
        : "+f"(c[0]), "+f"(c[1]), "+f"(c[2]), "+f"(c[3])
        : "r"(a0), "r"(a1), "r"(a2), "r"(a3), "r"(b0), "r"(b1));
}

// ---------------------------------------------------------------------------
// Fused projection GEMMs (TF32), all three in one launch (blockIdx.z picks).
// Identical to the round-3 passing kernel (298us).
// ---------------------------------------------------------------------------
__global__ __launch_bounds__(256)
void proj3_tf32(const float* __restrict__ Xq, const float* __restrict__ Xk,
                const float* __restrict__ Xv, const float* __restrict__ Wq,
                const float* __restrict__ Wk, const float* __restrict__ Wv,
                float* __restrict__ Oq, float* __restrict__ Ok,
                float* __restrict__ Ov) {
    __shared__ uint32_t As[128][36];   // [m][k] row-major tf32, stride 36
    __shared__ uint32_t Bs[32][136];   // [k][n] tf32, stride 136

    const int z = blockIdx.z;
    const float* X = (z == 0) ? Xq : (z == 1) ? Xk : Xv;
    const float* W = (z == 0) ? Wq : (z == 1) ? Wk : Wv;
    float* out     = (z == 0) ? Oq : (z == 1) ? Ok : Ov;

    const int tid  = threadIdx.x;
    const int warp = tid >> 5;
    const int lane = tid & 31;
    const int g    = lane >> 2;
    const int tg   = lane & 3;

    const int bm = blockIdx.y * 128;
    const int bn = blockIdx.x * 128;
    const int wm = (warp & 1) * 64;
    const int wn = (warp >> 1) * 32;

    float acc[4][4][4];
#pragma unroll
    for (int i = 0; i < 4; i++)
#pragma unroll
        for (int j = 0; j < 4; j++)
#pragma unroll
            for (int r = 0; r < 4; r++) acc[i][j][r] = 0.f;

    const int arow = tid >> 1;
    const int acol = (tid & 1) * 16;
    const int brow = tid >> 3;
    const int bcol = (tid & 7) * 16;

    for (int k0 = 0; k0 < KDIM; k0 += 32) {
#pragma unroll
        for (int u = 0; u < 4; u++) {
            float4 v = *(const float4*)(X + (size_t)(bm + arow) * KDIM +
                                        k0 + acol + u * 4);
            *(uint4*)&As[arow][acol + u * 4] = cvt4(v);
        }
#pragma unroll
        for (int u = 0; u < 4; u++) {
            float4 v = *(const float4*)(W + (size_t)(k0 + brow) * NDIM +
                                        bn + bcol + u * 4);
            *(uint4*)&Bs[brow][bcol + u * 4] = cvt4(v);
        }
        __syncthreads();

#pragma unroll
        for (int ks = 0; ks < 4; ks++) {
            uint32_t afr[4][4];
#pragma unroll
            for (int mf = 0; mf < 4; mf++) {
                const int mb = wm + mf * 16;
                afr[mf][0] = As[mb + g][ks * 8 + tg];
                afr[mf][1] = As[mb + g + 8][ks * 8 + tg];
                afr[mf][2] = As[mb + g][ks * 8 + tg + 4];
                afr[mf][3] = As[mb + g + 8][ks * 8 + tg + 4];
            }
            uint32_t bfr[4][2];
#pragma unroll
            for (int nf = 0; nf < 4; nf++) {
                const int nb = wn + nf * 8;
                bfr[nf][0] = Bs[ks * 8 + tg][nb + g];
                bfr[nf][1] = Bs[ks * 8 + tg + 4][nb + g];
            }
#pragma unroll
            for (int mf = 0; mf < 4; mf++)
#pragma unroll
                for (int nf = 0; nf < 4; nf++)
                    mma_tf32(acc[mf][nf], afr[mf][0], afr[mf][1], afr[mf][2],
                             afr[mf][3], bfr[nf][0], bfr[nf][1]);
        }
        __syncthreads();
    }

#pragma unroll
    for (int mf = 0; mf < 4; mf++) {
#pragma unroll
        for (int nf = 0; nf < 4; nf++) {
            const int n = bn + wn + nf * 8 + tg * 2;
            const int h = n >> 6, e = n & 63;
#pragma unroll
            for (int half = 0; half < 2; half++) {
                const int m  = bm + wm + mf * 16 + g + half * 8;
                const int bt = m >> 9, l = m & 511;
                float* p = out + (((size_t)(bt << 3) + h) * L_ + l) * 64 + e;
                p[0] = acc[mf][nf][half * 2 + 0];
                p[1] = acc[mf][nf][half * 2 + 1];
            }
        }
    }
}

// ---------------------------------------------------------------------------
// Flash attention (TF32 MMA), one block per (bt, h, 128 q-rows).
// 4 warps; warp w owns 32 q-rows = TWO 16-row mma tiles. Each K/V B-fragment
// is loaded once and used for both M-tiles -> K/V fragment LDS bytes halved
// vs the 16-row/warp version. Q lives in a persistent smem tile.
// Strides: Qs/Ks/Ps 68 (4 mod 32), Vs 72 (8 mod 32) -> conflict-free frags.
// ---------------------------------------------------------------------------
#define QS_STR 68
#define KS_STR 68
#define VS_STR 72
#define PS_STR 68
#define OFF_KS (128 * QS_STR)                 // 8704
#define OFF_VS (OFF_KS + 64 * KS_STR)         // 13056
#define OFF_PS (OFF_VS + 64 * VS_STR)         // 17664
#define ATTN_SMEM ((OFF_PS + 128 * PS_STR) * 4)   // 105472 B

__global__ __launch_bounds__(128)
void attn_tf32(const float* __restrict__ Qg, const float* __restrict__ Kg,
               const float* __restrict__ Vg, const float* __restrict__ mask,
               const float* __restrict__ w_head, const float* __restrict__ tau,
               const float* __restrict__ delta, float* __restrict__ Og) {
    extern __shared__ uint32_t smu[];
    uint32_t (*Qs)[QS_STR] = (uint32_t(*)[QS_STR])smu;
    uint32_t (*Ks)[KS_STR] = (uint32_t(*)[KS_STR])(smu + OFF_KS);
    uint32_t (*Vs)[VS_STR] = (uint32_t(*)[VS_STR])(smu + OFF_VS);
    uint32_t (*Ps)[PS_STR] = (uint32_t(*)[PS_STR])(smu + OFF_PS);

    const int tid  = threadIdx.x;
    const int warp = tid >> 5;
    const int lane = tid & 31;
    const int g    = lane >> 2;
    const int tg   = lane & 3;
    const int wrow = warp * 32;          // warp owns q-rows [wrow, wrow+32)

    const int qt = blockIdx.x;           // 0..3  (128 q-rows each)
    const int h  = blockIdx.y;
    const int bt = blockIdx.z;
    const int r0 = qt * 128;

    const float scale = 0.125f;
    const float t1 = tau[0] * scale;
    const float t2 = delta[0] * scale;
    const float wh = w_head[h];

    const size_t headBase = ((size_t)(bt * H_ + h)) * L_ * 64;

    // ---- stage Q tile (128x64, scaled by t1, tf32): one row per thread ----
    {
        const float* Qp = Qg + headBase + (size_t)(r0 + tid) * 64;
#pragma unroll
        for (int u = 0; u < 16; u++) {
            float4 v = *(const float4*)(Qp + u * 4);
            v.x *= t1; v.y *= t1; v.z *= t1; v.w *= t1;
            *(uint4*)&Qs[tid][u * 4] = cvt4(v);
        }
    }
    __syncthreads();

    // softmax state per thread: rows (wrow + mt*16 + g) and (+8), mt=0,1
    float mA[2] = {-3.0e38f, -3.0e38f};   // row g
    float mB[2] = {-3.0e38f, -3.0e38f};   // row g+8
    float lA[2] = {0.f, 0.f};
    float lB[2] = {0.f, 0.f};

    float o[2][8][4];
#pragma unroll
    for (int mt = 0; mt < 2; mt++)
#pragma unroll
        for (int nf = 0; nf < 8; nf++)
#pragma unroll
            for (int r = 0; r < 4; r++) o[mt][nf][r] = 0.f;

    const int lr = tid >> 1;             // 0..63 (K/V staging row)
    const int lc = (tid & 1) * 32;

    for (int kc = 0; kc < 8; kc++) {
        // ---- stage K and V chunks (natural [s][e], tf32) ----
        const float* Kp = Kg + headBase + (size_t)(kc * 64 + lr) * 64 + lc;
        const float* Vp = Vg + headBase + (size_t)(kc * 64 + lr) * 64 + lc;
#pragma unroll
        for (int u = 0; u < 8; u++) {
            *(uint4*)&Ks[lr][lc + u * 4] = cvt4(*(const float4*)(Kp + u * 4));
            *(uint4*)&Vs[lr][lc + u * 4] = cvt4(*(const float4*)(Vp + u * 4));
        }
        __syncthreads();

        // ---- S = (Q*t1) K^T : 32x64 per warp, K frags shared by 2 M-tiles --
        float s[2][8][4];
#pragma unroll
        for (int mt = 0; mt < 2; mt++)
#pragma unroll
            for (int nf = 0; nf < 8; nf++)
#pragma unroll
                for (int r = 0; r < 4; r++) s[mt][nf][r] = 0.f;

#pragma unroll
        for (int ks = 0; ks < 8; ks++) {
            uint32_t qa[2][4];
#pragma unroll
            for (int mt = 0; mt < 2; mt++) {
                const int rb = wrow + mt * 16;
                qa[mt][0] = Qs[rb + g][ks * 8 + tg];
                qa[mt][1] = Qs[rb + g + 8][ks * 8 + tg];
                qa[mt][2] = Qs[rb + g][ks * 8 + tg + 4];
                qa[mt][3] = Qs[rb + g + 8][ks * 8 + tg + 4];
            }
#pragma unroll
            for (int nf = 0; nf < 8; nf++) {
                const uint32_t b0 = Ks[nf * 8 + g][ks * 8 + tg];
                const uint32_t b1 = Ks[nf * 8 + g][ks * 8 + tg + 4];
                mma_tf32(s[0][nf], qa[0][0], qa[0][1], qa[0][2], qa[0][3],
                         b0, b1);
                mma_tf32(s[1][nf], qa[1][0], qa[1][1], qa[1][2], qa[1][3],
                         b0, b1);
            }
        }

        // ---- epilogue + online softmax + P store + PV, per M-tile ----
#pragma unroll
        for (int mt = 0; mt < 2; mt++) {
            const int rlo = r0 + wrow + mt * 16 + g;
            // +t2, *mask
#pragma unroll
            for (int nf = 0; nf < 8; nf++) {
                const int c0 = kc * 64 + nf * 8 + tg * 2;
                const float2 mk0 =
                    *(const float2*)(mask + (size_t)rlo * L_ + c0);
                const float2 mk1 =
                    *(const float2*)(mask + (size_t)(rlo + 8) * L_ + c0);
                s[mt][nf][0] = (s[mt][nf][0] + t2) * mk0.x;
                s[mt][nf][1] = (s[mt][nf][1] + t2) * mk0.y;
                s[mt][nf][2] = (s[mt][nf][2] + t2) * mk1.x;
                s[mt][nf][3] = (s[mt][nf][3] + t2) * mk1.y;
            }

            float mx0 = -3.0e38f, mx1 = -3.0e38f;
#pragma unroll
            for (int nf = 0; nf < 8; nf++) {
                mx0 = fmaxf(mx0, fmaxf(s[mt][nf][0], s[mt][nf][1]));
                mx1 = fmaxf(mx1, fmaxf(s[mt][nf][2], s[mt][nf][3]));
            }
            mx0 = fmaxf(mx0, __shfl_xor_sync(0xffffffffu, mx0, 1));
            mx0 = fmaxf(mx0, __shfl_xor_sync(0xffffffffu, mx0, 2));
            mx1 = fmaxf(mx1, __shfl_xor_sync(0xffffffffu, mx1, 1));
            mx1 = fmaxf(mx1, __shfl_xor_sync(0xffffffffu, mx1, 2));

            const float mn0 = fmaxf(mA[mt], mx0);
            const float mn1 = fmaxf(mB[mt], mx1);
            const float al0 = __expf(mA[mt] - mn0);
            const float al1 = __expf(mB[mt] - mn1);

            float sum0 = 0.f, sum1 = 0.f;
#pragma unroll
            for (int nf = 0; nf < 8; nf++) {
                s[mt][nf][0] = __expf(s[mt][nf][0] - mn0);
                s[mt][nf][1] = __expf(s[mt][nf][1] - mn0);
                s[mt][nf][2] = __expf(s[mt][nf][2] - mn1);
                s[mt][nf][3] = __expf(s[mt][nf][3] - mn1);
                sum0 += s[mt][nf][0] + s[mt][nf][1];
                sum1 += s[mt][nf][2] + s[mt][nf][3];
            }
            sum0 += __shfl_xor_sync(0xffffffffu, sum0, 1);
            sum0 += __shfl_xor_sync(0xffffffffu, sum0, 2);
            sum1 += __shfl_xor_sync(0xffffffffu, sum1, 1);
            sum1 += __shfl_xor_sync(0xffffffffu, sum1, 2);

            lA[mt] = lA[mt] * al0 + sum0;  mA[mt] = mn0;
            lB[mt] = lB[mt] * al1 + sum1;  mB[mt] = mn1;

#pragma unroll
            for (int nf = 0; nf < 8; nf++) {
                o[mt][nf][0] *= al0; o[mt][nf][1] *= al0;
                o[mt][nf][2] *= al1; o[mt][nf][3] *= al1;
            }

            // P -> smem (own rows only; no barrier needed before reading back)
            const int rb = wrow + mt * 16;
#pragma unroll
            for (int nf = 0; nf < 8; nf++) {
                const int c = nf * 8 + tg * 2;
                uint2 plo, phi;
                plo.x = f2tf32(s[mt][nf][0]); plo.y = f2tf32(s[mt][nf][1]);
                phi.x = f2tf32(s[mt][nf][2]); phi.y = f2tf32(s[mt][nf][3]);
                *(uint2*)&Ps[rb + g][c]     = plo;
                *(uint2*)&Ps[rb + g + 8][c] = phi;
            }
        }

        // ---- O += P V : V frags shared by 2 M-tiles ----
#pragma unroll
        for (int ks = 0; ks < 8; ks++) {
            uint32_t pa[2][4];
#pragma unroll
            for (int mt = 0; mt < 2; mt++) {
                const int rb = wrow + mt * 16;
                pa[mt][0] = Ps[rb + g][ks * 8 + tg];
                pa[mt][1] = Ps[rb + g + 8][ks * 8 + tg];
                pa[mt][2] = Ps[rb + g][ks * 8 + tg + 4];
                pa[mt][3] = Ps[rb + g + 8][ks * 8 + tg + 4];
            }
#pragma unroll
            for (int nf = 0; nf < 8; nf++) {
                const uint32_t b0 = Vs[ks * 8 + tg][nf * 8 + g];
                const uint32_t b1 = Vs[ks * 8 + tg + 4][nf * 8 + g];
                mma_tf32(o[0][nf], pa[0][0], pa[0][1], pa[0][2], pa[0][3],
                         b0, b1);
                mma_tf32(o[1][nf], pa[1][0], pa[1][1], pa[1][2], pa[1][3],
                         b0, b1);
            }
        }
        __syncthreads();   // Ks/Vs consumed before next chunk overwrites
    }

    // ---- finalize: *(wh/l), write (bt,h,l,e) ----
    float* obase = Og + headBase;
#pragma unroll
    for (int mt = 0; mt < 2; mt++) {
        const float i0 = wh / lA[mt];
        const float i1 = wh / lB[mt];
        const int rlo = r0 + wrow + mt * 16 + g;
#pragma unroll
        for (int nf = 0; nf < 8; nf++) {
            const int e = nf * 8 + tg * 2;
            float2 v0 = make_float2(o[mt][nf][0] * i0, o[mt][nf][1] * i0);
            float2 v1 = make_float2(o[mt][nf][2] * i1, o[mt][nf][3] * i1);
            *(float2*)(obase + (size_t)rlo * 64 + e)       = v0;
            *(float2*)(obase + (size_t)(rlo + 8) * 64 + e) = v1;
        }
    }
}

// ---------------------------------------------------------------------------
// Head combine: out[bt,l,e] = sum_h O[bt,h,l,e]   (w_h already folded in)
// ---------------------------------------------------------------------------
__global__ __launch_bounds__(256)
void combine_heads(const float* __restrict__ O, float* __restrict__ out) {
    const int idx = blockIdx.x * 256 + threadIdx.x;
    const int btl = idx >> 4;
    const int e   = (idx & 15) * 4;
    const int bt  = btl >> 9;
    const int l   = btl & 511;

    float4 acc = make_float4(0.f, 0.f, 0.f, 0.f);
#pragma unroll
    for (int h = 0; h < H_; h++) {
        const float4 v = *(const float4*)(O +
            (((size_t)(bt * H_ + h)) * L_ + l) * 64 + e);
        acc.x += v.x; acc.y += v.y; acc.z += v.z; acc.w += v.w;
    }
    *(float4*)(out + (size_t)btl * 64 + e) = acc;
}

// ---------------------------------------------------------------------------
extern "C" void kernel_launch(void* const* d_in, const int* in_sizes, int n_in,
                              void* d_out, int out_size) {
    const float* queries = (const float*)d_in[0];
    const float* keys    = (const float*)d_in[1];
    const float* values  = (const float*)d_in[2];
    const float* mask    = (const float*)d_in[3];
    const float* Wq      = (const float*)d_in[4];
    const float* Wk      = (const float*)d_in[5];
    const float* Wv      = (const float*)d_in[6];
    const float* w_head  = (const float*)d_in[7];
    const float* tau     = (const float*)d_in[8];
    const float* delta   = (const float*)d_in[9];
    float* out = (float*)d_out;

    float *qs, *ks, *vs, *os;
    cudaGetSymbolAddress((void**)&qs, g_Q);
    cudaGetSymbolAddress((void**)&ks, g_K);
    cudaGetSymbolAddress((void**)&vs, g_V);
    cudaGetSymbolAddress((void**)&os, g_O);

    dim3 gp(NDIM / 128, M_TOT / 128, 3);   // (4, 128, 3) — fused Q/K/V proj
    proj3_tf32<<<gp, 256>>>(queries, keys, values, Wq, Wk, Wv, qs, ks, vs);

    cudaFuncSetAttribute(attn_tf32,
                         cudaFuncAttributeMaxDynamicSharedMemorySize,
                         ATTN_SMEM);
    dim3 ga(L_ / 128, H_, BT_);            // (4, 8, 32)
    attn_tf32<<<ga, 128, ATTN_SMEM>>>(qs, ks, vs, mask, w_head, tau, delta, os);

    combine_heads<<<1024, 256>>>(os, out);
}

// round 12
// speedup vs baseline: 2.7909x; 1.0238x over previous
#include <cuda_runtime.h>
#include <cuda_bf16.h>
#include <cstdint>

// Problem constants
#define B_  4
#define T_  8
#define L_  512
#define D_  512
#define H_  8
#define BT_ 32            // B_*T_
#define M_TOT 16384       // BT_*L_
#define NDIM 512          // H_*64
#define KDIM 512          // D_

// Scratch (device globals: allocation-guard safe)
__device__ float g_Q[BT_ * H_ * L_ * 64];
__device__ float g_K[BT_ * H_ * L_ * 64];
__device__ float g_V[BT_ * H_ * L_ * 64];
__device__ float g_O[BT_ * H_ * L_ * 64];   // per-head weighted attention out

// ---------------------------------------------------------------------------
// helpers
// ---------------------------------------------------------------------------
__device__ __forceinline__ uint32_t f2tf32(float f) {
    uint32_t u;
    asm("cvt.rna.tf32.f32 %0, %1;" : "=r"(u) : "f"(f));
    return u;
}

__device__ __forceinline__ uint4 cvt4(float4 v) {
    uint4 r;
    r.x = f2tf32(v.x); r.y = f2tf32(v.y);
    r.z = f2tf32(v.z); r.w = f2tf32(v.w);
    return r;
}

__device__ __forceinline__ void mma_tf32(float c[4],
                                         uint32_t a0, uint32_t a1,
                                         uint32_t a2, uint32_t a3,
                                         uint32_t b0, uint32_t b1) {
    asm volatile(
        "mma.sync.aligned.m16n8k8.row.col.f32.tf32.tf32.f32 "
        "{%0,%1,%2,%3}, {%4,%5,%6,%7}, {%8,%9}, {%0,%1,%2,%3};\n"
        : "+f"(c[0]), "+f"(c[1]), "+f"(c[2]), "+f"(c[3])
        : "f"(__uint_as_float(a0)), "f"(__uint_as_float(a1)),
          "f"(__uint_as_float(a2)), "f"(__uint_as_float(a3)),
          "f"(__uint_as_float(b0)), "f"(__uint_as_float(b1)));
}

__device__ __forceinline__ uint32_t smem_u32(const void* p) {
    uint32_t a;
    asm("{ .reg .u64 t; cvta.to.shared.u64 t, %1; cvt.u32.u64 %0, t; }"
        : "=r"(a) : "l"(p));
    return a;
}

__device__ __forceinline__ void cpa16(uint32_t dst, const float* src) {
    asm volatile("cp.async.cg.shared.global [%0], [%1], 16;\n"
                 :: "r"(dst), "l"(src));
}
#define CP_COMMIT() asm volatile("cp.async.commit_group;\n" ::: "memory")
#define CP_WAIT0()  asm volatile("cp.async.wait_group 0;\n" ::: "memory")

// ---------------------------------------------------------------------------
// Fused projection GEMMs (TF32 MMA + cp.async double buffering).
// C[m,n] = sum_k X[m,k]*W[k,n], M=16384, N=512, K=512; z picks Q/K/V.
// Block 128x128, k-chunk 32, 8 warps; warp tile 64(M)x32(N).
// Raw fp32 staged via cp.async; tf32 convert happens on the fragment
// registers right before the MMA (numerically identical to staging-time cvt).
// A [m][k] stride 36 (4 mod 32), B [k][n] stride 136 (8 mod 32) -> both
// fragment patterns conflict-free. One barrier per k-iteration.
// ---------------------------------------------------------------------------
#define PA_STR 36
#define PB_STR 136
#define OFF_BS (2 * 128 * PA_STR)                    // floats
#define PROJ_SMEM ((OFF_BS + 2 * 32 * PB_STR) * 4)   // 71680 B

__global__ __launch_bounds__(256)
void proj3_cp(const float* __restrict__ Xq, const float* __restrict__ Xk,
              const float* __restrict__ Xv, const float* __restrict__ Wq,
              const float* __restrict__ Wk, const float* __restrict__ Wv,
              float* __restrict__ Oq, float* __restrict__ Ok,
              float* __restrict__ Ov) {
    extern __shared__ float smf[];
    const int z = blockIdx.z;
    const float* X = (z == 0) ? Xq : (z == 1) ? Xk : Xv;
    const float* W = (z == 0) ? Wq : (z == 1) ? Wk : Wv;
    float* out     = (z == 0) ? Oq : (z == 1) ? Ok : Ov;

    const int tid  = threadIdx.x;
    const int warp = tid >> 5;
    const int lane = tid & 31;
    const int g    = lane >> 2;
    const int tg   = lane & 3;

    const int bm = blockIdx.y * 128;
    const int bn = blockIdx.x * 128;
    const int wm = (warp & 1) * 64;
    const int wn = (warp >> 1) * 32;

    float acc[4][4][4];
#pragma unroll
    for (int i = 0; i < 4; i++)
#pragma unroll
        for (int j = 0; j < 4; j++)
#pragma unroll
            for (int r = 0; r < 4; r++) acc[i][j][r] = 0.f;

    // staging coordinates
    const int arow = tid >> 1;           // 0..127
    const int acol = (tid & 1) * 16;     // 0 or 16
    const int brow = tid >> 3;           // 0..31
    const int bcol = (tid & 7) * 16;     // 0..112

    const uint32_t sbase = smem_u32(smf);
    // smem addresses of this thread's staging slots, per buffer
    uint32_t adst[2], bdst[2];
#pragma unroll
    for (int b = 0; b < 2; b++) {
        adst[b] = sbase + (uint32_t)(b * 128 * PA_STR + arow * PA_STR + acol) * 4;
        bdst[b] = sbase + (uint32_t)(OFF_BS + b * 32 * PB_STR +
                                     brow * PB_STR + bcol) * 4;
    }
    const float* asrc = X + (size_t)(bm + arow) * KDIM + acol;
    const float* bsrc = W + (size_t)brow * NDIM + bn + bcol;

    // prefetch tile 0 into buffer 0
#pragma unroll
    for (int u = 0; u < 4; u++) cpa16(adst[0] + u * 16, asrc + u * 4);
#pragma unroll
    for (int u = 0; u < 4; u++) cpa16(bdst[0] + u * 16, bsrc + u * 4);
    CP_COMMIT();

    for (int c = 0; c < 16; c++) {
        const int buf = c & 1;
        CP_WAIT0();
        __syncthreads();   // buffer `buf` ready; previous compute done

        if (c < 15) {
            const int nb = (c + 1) & 1;
            const float* an = asrc + (c + 1) * 32;
            const float* bn_ = bsrc + (size_t)(c + 1) * 32 * NDIM;
#pragma unroll
            for (int u = 0; u < 4; u++) cpa16(adst[nb] + u * 16, an + u * 4);
#pragma unroll
            for (int u = 0; u < 4; u++) cpa16(bdst[nb] + u * 16, bn_ + u * 4);
            CP_COMMIT();
        }

        const float* Af = smf + buf * 128 * PA_STR;
        const float* Bf = smf + OFF_BS + buf * 32 * PB_STR;

#pragma unroll
        for (int ks = 0; ks < 4; ks++) {
            uint32_t afr[4][4];
#pragma unroll
            for (int mf = 0; mf < 4; mf++) {
                const int mb = wm + mf * 16;
                afr[mf][0] = f2tf32(Af[(mb + g) * PA_STR + ks * 8 + tg]);
                afr[mf][1] = f2tf32(Af[(mb + g + 8) * PA_STR + ks * 8 + tg]);
                afr[mf][2] = f2tf32(Af[(mb + g) * PA_STR + ks * 8 + tg + 4]);
                afr[mf][3] = f2tf32(Af[(mb + g + 8) * PA_STR + ks * 8 + tg + 4]);
            }
            uint32_t bfr[4][2];
#pragma unroll
            for (int nf = 0; nf < 4; nf++) {
                const int nb2 = wn + nf * 8;
                bfr[nf][0] = f2tf32(Bf[(ks * 8 + tg) * PB_STR + nb2 + g]);
                bfr[nf][1] = f2tf32(Bf[(ks * 8 + tg + 4) * PB_STR + nb2 + g]);
            }
#pragma unroll
            for (int mf = 0; mf < 4; mf++)
#pragma unroll
                for (int nf = 0; nf < 4; nf++)
                    mma_tf32(acc[mf][nf], afr[mf][0], afr[mf][1], afr[mf][2],
                             afr[mf][3], bfr[nf][0], bfr[nf][1]);
        }
    }

    // Epilogue with (bt,h,l,e) remap
#pragma unroll
    for (int mf = 0; mf < 4; mf++) {
#pragma unroll
        for (int nf = 0; nf < 4; nf++) {
            const int n = bn + wn + nf * 8 + tg * 2;
            const int h = n >> 6, e = n & 63;
#pragma unroll
            for (int half = 0; half < 2; half++) {
                const int m  = bm + wm + mf * 16 + g + half * 8;
                const int bt = m >> 9, l = m & 511;
                float* p = out + (((size_t)(bt << 3) + h) * L_ + l) * 64 + e;
                p[0] = acc[mf][nf][half * 2 + 0];
                p[1] = acc[mf][nf][half * 2 + 1];
            }
        }
    }
}

// ---------------------------------------------------------------------------
// Flash attention (TF32 MMA) — unchanged from round 11 (passing, 7.67e-4).
// One block per (bt, h, 128 q-rows); 4 warps, 32 q-rows/warp (2 M-tiles).
// ---------------------------------------------------------------------------
#define QS_STR 68
#define KS_STR 68
#define VS_STR 72
#define PS_STR 68
#define OFF_KS (128 * QS_STR)
#define OFF_VS (OFF_KS + 64 * KS_STR)
#define OFF_PS (OFF_VS + 64 * VS_STR)
#define ATTN_SMEM ((OFF_PS + 128 * PS_STR) * 4)

__global__ __launch_bounds__(128)
void attn_tf32(const float* __restrict__ Qg, const float* __restrict__ Kg,
               const float* __restrict__ Vg, const float* __restrict__ mask,
               const float* __restrict__ w_head, const float* __restrict__ tau,
               const float* __restrict__ delta, float* __restrict__ Og) {
    extern __shared__ uint32_t smu[];
    uint32_t (*Qs)[QS_STR] = (uint32_t(*)[QS_STR])smu;
    uint32_t (*Ks)[KS_STR] = (uint32_t(*)[KS_STR])(smu + OFF_KS);
    uint32_t (*Vs)[VS_STR] = (uint32_t(*)[VS_STR])(smu + OFF_VS);
    uint32_t (*Ps)[PS_STR] = (uint32_t(*)[PS_STR])(smu + OFF_PS);

    const int tid  = threadIdx.x;
    const int warp = tid >> 5;
    const int lane = tid & 31;
    const int g    = lane >> 2;
    const int tg   = lane & 3;
    const int wrow = warp * 32;

    const int qt = blockIdx.x;
    const int h  = blockIdx.y;
    const int bt = blockIdx.z;
    const int r0 = qt * 128;

    const float scale = 0.125f;
    const float t1 = tau[0] * scale;
    const float t2 = delta[0] * scale;
    const float wh = w_head[h];

    const size_t headBase = ((size_t)(bt * H_ + h)) * L_ * 64;

    {
        const float* Qp = Qg + headBase + (size_t)(r0 + tid) * 64;
#pragma unroll
        for (int u = 0; u < 16; u++) {
            float4 v = *(const float4*)(Qp + u * 4);
            v.x *= t1; v.y *= t1; v.z *= t1; v.w *= t1;
            *(uint4*)&Qs[tid][u * 4] = cvt4(v);
        }
    }
    __syncthreads();

    float mA[2] = {-3.0e38f, -3.0e38f};
    float mB[2] = {-3.0e38f, -3.0e38f};
    float lA[2] = {0.f, 0.f};
    float lB[2] = {0.f, 0.f};

    float o[2][8][4];
#pragma unroll
    for (int mt = 0; mt < 2; mt++)
#pragma unroll
        for (int nf = 0; nf < 8; nf++)
#pragma unroll
            for (int r = 0; r < 4; r++) o[mt][nf][r] = 0.f;

    const int lr = tid >> 1;
    const int lc = (tid & 1) * 32;

    for (int kc = 0; kc < 8; kc++) {
        const float* Kp = Kg + headBase + (size_t)(kc * 64 + lr) * 64 + lc;
        const float* Vp = Vg + headBase + (size_t)(kc * 64 + lr) * 64 + lc;
#pragma unroll
        for (int u = 0; u < 8; u++) {
            *(uint4*)&Ks[lr][lc + u * 4] = cvt4(*(const float4*)(Kp + u * 4));
            *(uint4*)&Vs[lr][lc + u * 4] = cvt4(*(const float4*)(Vp + u * 4));
        }
        __syncthreads();

        float s[2][8][4];
#pragma unroll
        for (int mt = 0; mt < 2; mt++)
#pragma unroll
            for (int nf = 0; nf < 8; nf++)
#pragma unroll
                for (int r = 0; r < 4; r++) s[mt][nf][r] = 0.f;

#pragma unroll
        for (int ks = 0; ks < 8; ks++) {
            uint32_t qa[2][4];
#pragma unroll
            for (int mt = 0; mt < 2; mt++) {
                const int rb = wrow + mt * 16;
                qa[mt][0] = Qs[rb + g][ks * 8 + tg];
                qa[mt][1] = Qs[rb + g + 8][ks * 8 + tg];
                qa[mt][2] = Qs[rb + g][ks * 8 + tg + 4];
                qa[mt][3] = Qs[rb + g + 8][ks * 8 + tg + 4];
            }
#pragma unroll
            for (int nf = 0; nf < 8; nf++) {
                const uint32_t b0 = Ks[nf * 8 + g][ks * 8 + tg];
                const uint32_t b1 = Ks[nf * 8 + g][ks * 8 + tg + 4];
                mma_tf32(s[0][nf], qa[0][0], qa[0][1], qa[0][2], qa[0][3],
                         b0, b1);
                mma_tf32(s[1][nf], qa[1][0], qa[1][1], qa[1][2], qa[1][3],
                         b0, b1);
            }
        }

#pragma unroll
        for (int mt = 0; mt < 2; mt++) {
            const int rlo = r0 + wrow + mt * 16 + g;
#pragma unroll
            for (int nf = 0; nf < 8; nf++) {
                const int c0 = kc * 64 + nf * 8 + tg * 2;
                const float2 mk0 =
                    *(const float2*)(mask + (size_t)rlo * L_ + c0);
                const float2 mk1 =
                    *(const float2*)(mask + (size_t)(rlo + 8) * L_ + c0);
                s[mt][nf][0] = (s[mt][nf][0] + t2) * mk0.x;
                s[mt][nf][1] = (s[mt][nf][1] + t2) * mk0.y;
                s[mt][nf][2] = (s[mt][nf][2] + t2) * mk1.x;
                s[mt][nf][3] = (s[mt][nf][3] + t2) * mk1.y;
            }

            float mx0 = -3.0e38f, mx1 = -3.0e38f;
#pragma unroll
            for (int nf = 0; nf < 8; nf++) {
                mx0 = fmaxf(mx0, fmaxf(s[mt][nf][0], s[mt][nf][1]));
                mx1 = fmaxf(mx1, fmaxf(s[mt][nf][2], s[mt][nf][3]));
            }
            mx0 = fmaxf(mx0, __shfl_xor_sync(0xffffffffu, mx0, 1));
            mx0 = fmaxf(mx0, __shfl_xor_sync(0xffffffffu, mx0, 2));
            mx1 = fmaxf(mx1, __shfl_xor_sync(0xffffffffu, mx1, 1));
            mx1 = fmaxf(mx1, __shfl_xor_sync(0xffffffffu, mx1, 2));

            const float mn0 = fmaxf(mA[mt], mx0);
            const float mn1 = fmaxf(mB[mt], mx1);
            const float al0 = __expf(mA[mt] - mn0);
            const float al1 = __expf(mB[mt] - mn1);

            float sum0 = 0.f, sum1 = 0.f;
#pragma unroll
            for (int nf = 0; nf < 8; nf++) {
                s[mt][nf][0] = __expf(s[mt][nf][0] - mn0);
                s[mt][nf][1] = __expf(s[mt][nf][1] - mn0);
                s[mt][nf][2] = __expf(s[mt][nf][2] - mn1);
                s[mt][nf][3] = __expf(s[mt][nf][3] - mn1);
                sum0 += s[mt][nf][0] + s[mt][nf][1];
                sum1 += s[mt][nf][2] + s[mt][nf][3];
            }
            sum0 += __shfl_xor_sync(0xffffffffu, sum0, 1);
            sum0 += __shfl_xor_sync(0xffffffffu, sum0, 2);
            sum1 += __shfl_xor_sync(0xffffffffu, sum1, 1);
            sum1 += __shfl_xor_sync(0xffffffffu, sum1, 2);

            lA[mt] = lA[mt] * al0 + sum0;  mA[mt] = mn0;
            lB[mt] = lB[mt] * al1 + sum1;  mB[mt] = mn1;

#pragma unroll
            for (int nf = 0; nf < 8; nf++) {
                o[mt][nf][0] *= al0; o[mt][nf][1] *= al0;
                o[mt][nf][2] *= al1; o[mt][nf][3] *= al1;
            }

            const int rb = wrow + mt * 16;
#pragma unroll
            for (int nf = 0; nf < 8; nf++) {
                const int c = nf * 8 + tg * 2;
                uint2 plo, phi;
                plo.x = f2tf32(s[mt][nf][0]); plo.y = f2tf32(s[mt][nf][1]);
                phi.x = f2tf32(s[mt][nf][2]); phi.y = f2tf32(s[mt][nf][3]);
                *(uint2*)&Ps[rb + g][c]     = plo;
                *(uint2*)&Ps[rb + g + 8][c] = phi;
            }
        }

#pragma unroll
        for (int ks = 0; ks < 8; ks++) {
            uint32_t pa[2][4];
#pragma unroll
            for (int mt = 0; mt < 2; mt++) {
                const int rb = wrow + mt * 16;
                pa[mt][0] = Ps[rb + g][ks * 8 + tg];
                pa[mt][1] = Ps[rb + g + 8][ks * 8 + tg];
                pa[mt][2] = Ps[rb + g][ks * 8 + tg + 4];
                pa[mt][3] = Ps[rb + g + 8][ks * 8 + tg + 4];
            }
#pragma unroll
            for (int nf = 0; nf < 8; nf++) {
                const uint32_t b0 = Vs[ks * 8 + tg][nf * 8 + g];
                const uint32_t b1 = Vs[ks * 8 + tg + 4][nf * 8 + g];
                mma_tf32(o[0][nf], pa[0][0], pa[0][1], pa[0][2], pa[0][3],
                         b0, b1);
                mma_tf32(o[1][nf], pa[1][0], pa[1][1], pa[1][2], pa[1][3],
                         b0, b1);
            }
        }
        __syncthreads();
    }

    float* obase = Og + headBase;
#pragma unroll
    for (int mt = 0; mt < 2; mt++) {
        const float i0 = wh / lA[mt];
        const float i1 = wh / lB[mt];
        const int rlo = r0 + wrow + mt * 16 + g;
#pragma unroll
        for (int nf = 0; nf < 8; nf++) {
            const int e = nf * 8 + tg * 2;
            float2 v0 = make_float2(o[mt][nf][0] * i0, o[mt][nf][1] * i0);
            float2 v1 = make_float2(o[mt][nf][2] * i1, o[mt][nf][3] * i1);
            *(float2*)(obase + (size_t)rlo * 64 + e)       = v0;
            *(float2*)(obase + (size_t)(rlo + 8) * 64 + e) = v1;
        }
    }
}

// ---------------------------------------------------------------------------
// Head combine: out[bt,l,e] = sum_h O[bt,h,l,e]   (w_h already folded in)
// ---------------------------------------------------------------------------
__global__ __launch_bounds__(256)
void combine_heads(const float* __restrict__ O, float* __restrict__ out) {
    const int idx = blockIdx.x * 256 + threadIdx.x;
    const int btl = idx >> 4;
    const int e   = (idx & 15) * 4;
    const int bt  = btl >> 9;
    const int l   = btl & 511;

    float4 acc = make_float4(0.f, 0.f, 0.f, 0.f);
#pragma unroll
    for (int h = 0; h < H_; h++) {
        const float4 v = *(const float4*)(O +
            (((size_t)(bt * H_ + h)) * L_ + l) * 64 + e);
        acc.x += v.x; acc.y += v.y; acc.z += v.z; acc.w += v.w;
    }
    *(float4*)(out + (size_t)btl * 64 + e) = acc;
}

// ---------------------------------------------------------------------------
extern "C" void kernel_launch(void* const* d_in, const int* in_sizes, int n_in,
                              void* d_out, int out_size) {
    const float* queries = (const float*)d_in[0];
    const float* keys    = (const float*)d_in[1];
    const float* values  = (const float*)d_in[2];
    const float* mask    = (const float*)d_in[3];
    const float* Wq      = (const float*)d_in[4];
    const float* Wk      = (const float*)d_in[5];
    const float* Wv      = (const float*)d_in[6];
    const float* w_head  = (const float*)d_in[7];
    const float* tau     = (const float*)d_in[8];
    const float* delta   = (const float*)d_in[9];
    float* out = (float*)d_out;

    float *qs, *ks, *vs, *os;
    cudaGetSymbolAddress((void**)&qs, g_Q);
    cudaGetSymbolAddress((void**)&ks, g_K);
    cudaGetSymbolAddress((void**)&vs, g_V);
    cudaGetSymbolAddress((void**)&os, g_O);

    cudaFuncSetAttribute(proj3_cp,
                         cudaFuncAttributeMaxDynamicSharedMemorySize,
                         PROJ_SMEM);
    dim3 gp(NDIM / 128, M_TOT / 128, 3);   // (4, 128, 3)
    proj3_cp<<<gp, 256, PROJ_SMEM>>>(queries, keys, values, Wq, Wk, Wv,
                                     qs, ks, vs);

    cudaFuncSetAttribute(attn_tf32,
                         cudaFuncAttributeMaxDynamicSharedMemorySize,
                         ATTN_SMEM);
    dim3 ga(L_ / 128, H_, BT_);            // (4, 8, 32)
    attn_tf32<<<ga, 128, ATTN_SMEM>>>(qs, ks, vs, mask, w_head, tau, delta, os);

    combine_heads<<<1024, 256>>>(os, out);
}

// round 14
// speedup vs baseline: 3.5492x; 1.2717x over previous
#include <cuda_runtime.h>
#include <cuda_bf16.h>
#include <cstdint>

// Problem constants
#define B_  4
#define T_  8
#define L_  512
#define D_  512
#define H_  8
#define BT_ 32            // B_*T_
#define M_TOT 16384       // BT_*L_
#define NDIM 512          // H_*64
#define KDIM 512          // D_

// Scratch (device globals: allocation-guard safe)
__device__ float g_Q[BT_ * H_ * L_ * 64];
__device__ float g_K[BT_ * H_ * L_ * 64];
__device__ float g_V[BT_ * H_ * L_ * 64];
__device__ float g_O[BT_ * H_ * L_ * 64];   // per-head weighted attention out

// ---------------------------------------------------------------------------
// helpers
// ---------------------------------------------------------------------------
__device__ __forceinline__ uint32_t f2tf32(float f) {
    uint32_t u;
    asm("cvt.rna.tf32.f32 %0, %1;" : "=r"(u) : "f"(f));
    return u;
}

__device__ __forceinline__ uint4 cvt4(float4 v) {
    uint4 r;
    r.x = f2tf32(v.x); r.y = f2tf32(v.y);
    r.z = f2tf32(v.z); r.w = f2tf32(v.w);
    return r;
}

__device__ __forceinline__ void mma_tf32(float c[4],
                                         uint32_t a0, uint32_t a1,
                                         uint32_t a2, uint32_t a3,
                                         uint32_t b0, uint32_t b1) {
    asm volatile(
        "mma.sync.aligned.m16n8k8.row.col.f32.tf32.tf32.f32 "
        "{%0,%1,%2,%3}, {%4,%5,%6,%7}, {%8,%9}, {%0,%1,%2,%3};\n"
        : "+f"(c[0]), "+f"(c[1]), "+f"(c[2]), "+f"(c[3])
        : "f"(__uint_as_float(a0)), "f"(__uint_as_float(a1)),
          "f"(__uint_as_float(a2)), "f"(__uint_as_float(a3)),
          "f"(__uint_as_float(b0)), "f"(__uint_as_float(b1)));
}

__device__ __forceinline__ uint32_t smem_u32(const void* p) {
    uint32_t a;
    asm("{ .reg .u64 t; cvta.to.shared.u64 t, %1; cvt.u32.u64 %0, t; }"
        : "=r"(a) : "l"(p));
    return a;
}

__device__ __forceinline__ void cpa16(uint32_t dst, const float* src) {
    asm volatile("cp.async.cg.shared.global [%0], [%1], 16;\n"
                 :: "r"(dst), "l"(src));
}
#define CP_COMMIT() asm volatile("cp.async.commit_group;\n" ::: "memory")
#define CP_WAIT0()  asm volatile("cp.async.wait_group 0;\n" ::: "memory")

// ---------------------------------------------------------------------------
// Fused projection GEMMs (TF32 MMA + cp.async double buffering).
// Unchanged from round 12 (286us passing).
// ---------------------------------------------------------------------------
#define PA_STR 36
#define PB_STR 136
#define OFF_BS (2 * 128 * PA_STR)                    // floats
#define PROJ_SMEM ((OFF_BS + 2 * 32 * PB_STR) * 4)   // 71680 B

__global__ __launch_bounds__(256)
void proj3_cp(const float* __restrict__ Xq, const float* __restrict__ Xk,
              const float* __restrict__ Xv, const float* __restrict__ Wq,
              const float* __restrict__ Wk, const float* __restrict__ Wv,
              float* __restrict__ Oq, float* __restrict__ Ok,
              float* __restrict__ Ov) {
    extern __shared__ float smf[];
    const int z = blockIdx.z;
    const float* X = (z == 0) ? Xq : (z == 1) ? Xk : Xv;
    const float* W = (z == 0) ? Wq : (z == 1) ? Wk : Wv;
    float* out     = (z == 0) ? Oq : (z == 1) ? Ok : Ov;

    const int tid  = threadIdx.x;
    const int warp = tid >> 5;
    const int lane = tid & 31;
    const int g    = lane >> 2;
    const int tg   = lane & 3;

    const int bm = blockIdx.y * 128;
    const int bn = blockIdx.x * 128;
    const int wm = (warp & 1) * 64;
    const int wn = (warp >> 1) * 32;

    float acc[4][4][4];
#pragma unroll
    for (int i = 0; i < 4; i++)
#pragma unroll
        for (int j = 0; j < 4; j++)
#pragma unroll
            for (int r = 0; r < 4; r++) acc[i][j][r] = 0.f;

    const int arow = tid >> 1;
    const int acol = (tid & 1) * 16;
    const int brow = tid >> 3;
    const int bcol = (tid & 7) * 16;

    const uint32_t sbase = smem_u32(smf);
    uint32_t adst[2], bdst[2];
#pragma unroll
    for (int b = 0; b < 2; b++) {
        adst[b] = sbase + (uint32_t)(b * 128 * PA_STR + arow * PA_STR + acol) * 4;
        bdst[b] = sbase + (uint32_t)(OFF_BS + b * 32 * PB_STR +
                                     brow * PB_STR + bcol) * 4;
    }
    const float* asrc = X + (size_t)(bm + arow) * KDIM + acol;
    const float* bsrc = W + (size_t)brow * NDIM + bn + bcol;

#pragma unroll
    for (int u = 0; u < 4; u++) cpa16(adst[0] + u * 16, asrc + u * 4);
#pragma unroll
    for (int u = 0; u < 4; u++) cpa16(bdst[0] + u * 16, bsrc + u * 4);
    CP_COMMIT();

    for (int c = 0; c < 16; c++) {
        const int buf = c & 1;
        CP_WAIT0();
        __syncthreads();

        if (c < 15) {
            const int nb = (c + 1) & 1;
            const float* an = asrc + (c + 1) * 32;
            const float* bn_ = bsrc + (size_t)(c + 1) * 32 * NDIM;
#pragma unroll
            for (int u = 0; u < 4; u++) cpa16(adst[nb] + u * 16, an + u * 4);
#pragma unroll
            for (int u = 0; u < 4; u++) cpa16(bdst[nb] + u * 16, bn_ + u * 4);
            CP_COMMIT();
        }

        const float* Af = smf + buf * 128 * PA_STR;
        const float* Bf = smf + OFF_BS + buf * 32 * PB_STR;

#pragma unroll
        for (int ks = 0; ks < 4; ks++) {
            uint32_t afr[4][4];
#pragma unroll
            for (int mf = 0; mf < 4; mf++) {
                const int mb = wm + mf * 16;
                afr[mf][0] = f2tf32(Af[(mb + g) * PA_STR + ks * 8 + tg]);
                afr[mf][1] = f2tf32(Af[(mb + g + 8) * PA_STR + ks * 8 + tg]);
                afr[mf][2] = f2tf32(Af[(mb + g) * PA_STR + ks * 8 + tg + 4]);
                afr[mf][3] = f2tf32(Af[(mb + g + 8) * PA_STR + ks * 8 + tg + 4]);
            }
            uint32_t bfr[4][2];
#pragma unroll
            for (int nf = 0; nf < 4; nf++) {
                const int nb2 = wn + nf * 8;
                bfr[nf][0] = f2tf32(Bf[(ks * 8 + tg) * PB_STR + nb2 + g]);
                bfr[nf][1] = f2tf32(Bf[(ks * 8 + tg + 4) * PB_STR + nb2 + g]);
            }
#pragma unroll
            for (int mf = 0; mf < 4; mf++)
#pragma unroll
                for (int nf = 0; nf < 4; nf++)
                    mma_tf32(acc[mf][nf], afr[mf][0], afr[mf][1], afr[mf][2],
                             afr[mf][3], bfr[nf][0], bfr[nf][1]);
        }
    }

#pragma unroll
    for (int mf = 0; mf < 4; mf++) {
#pragma unroll
        for (int nf = 0; nf < 4; nf++) {
            const int n = bn + wn + nf * 8 + tg * 2;
            const int h = n >> 6, e = n & 63;
#pragma unroll
            for (int half = 0; half < 2; half++) {
                const int m  = bm + wm + mf * 16 + g + half * 8;
                const int bt = m >> 9, l = m & 511;
                float* p = out + (((size_t)(bt << 3) + h) * L_ + l) * 64 + e;
                p[0] = acc[mf][nf][half * 2 + 0];
                p[1] = acc[mf][nf][half * 2 + 1];
            }
        }
    }
}

// ---------------------------------------------------------------------------
// Flash attention (TF32 MMA + cp.async double-buffered K/V pipeline).
// One block per (bt, h, 128 q-rows); 4 warps, 32 q-rows/warp (2 M-tiles).
// K/V streamed in 32-key chunks (16 chunks), raw fp32 via cp.async into
// ping-pong buffers; tf32 convert on fragment registers (numerics identical).
// Q staged once (tf32, stride 68). P stride 36. One barrier per chunk.
// ---------------------------------------------------------------------------
#define QS_STR 68
#define KC_STR 68
#define VC_STR 72
#define PS_STR 36
#define OFF_KB (128 * QS_STR)                  // words: 8704
#define OFF_VB (OFF_KB + 2 * 32 * KC_STR)      // 13056
#define OFF_PSW (OFF_VB + 2 * 32 * VC_STR)     // 17664
#define ATTN_SMEM ((OFF_PSW + 128 * PS_STR) * 4)   // 89088 B

__global__ __launch_bounds__(128)
void attn_tf32(const float* __restrict__ Qg, const float* __restrict__ Kg,
               const float* __restrict__ Vg, const float* __restrict__ mask,
               const float* __restrict__ w_head, const float* __restrict__ tau,
               const float* __restrict__ delta, float* __restrict__ Og) {
    extern __shared__ float smf[];
    uint32_t* smu = (uint32_t*)smf;
    uint32_t (*Qs)[QS_STR] = (uint32_t(*)[QS_STR])smu;
    uint32_t (*Ps)[PS_STR] = (uint32_t(*)[PS_STR])(smu + OFF_PSW);

    const int tid  = threadIdx.x;
    const int warp = tid >> 5;
    const int lane = tid & 31;
    const int g    = lane >> 2;
    const int tg   = lane & 3;
    const int wrow = warp * 32;

    const int qt = blockIdx.x;
    const int h  = blockIdx.y;
    const int bt = blockIdx.z;
    const int r0 = qt * 128;

    const float scale = 0.125f;
    const float t1 = tau[0] * scale;
    const float t2 = delta[0] * scale;
    const float wh = w_head[h];

    const size_t headBase = ((size_t)(bt * H_ + h)) * L_ * 64;

    // ---- stage Q tile (128x64, scaled by t1, tf32): one row per thread ----
    {
        const float* Qp = Qg + headBase + (size_t)(r0 + tid) * 64;
#pragma unroll
        for (int u = 0; u < 16; u++) {
            float4 v = *(const float4*)(Qp + u * 4);
            v.x *= t1; v.y *= t1; v.z *= t1; v.w *= t1;
            *(uint4*)&Qs[tid][u * 4] = cvt4(v);
        }
    }

    // cp.async staging coords: 4 threads per key row (32 rows x 64 cols)
    const int slr = tid >> 2;            // 0..31
    const int slc = (tid & 3) * 16;      // 0,16,32,48
    const uint32_t sbase = smem_u32(smf);
    uint32_t kdst[2], vdst[2];
#pragma unroll
    for (int b = 0; b < 2; b++) {
        kdst[b] = sbase + (uint32_t)(OFF_KB + b * 32 * KC_STR +
                                     slr * KC_STR + slc) * 4;
        vdst[b] = sbase + (uint32_t)(OFF_VB + b * 32 * VC_STR +
                                     slr * VC_STR + slc) * 4;
    }
    const float* ksrc = Kg + headBase + (size_t)slr * 64 + slc;
    const float* vsrc = Vg + headBase + (size_t)slr * 64 + slc;

    // prefetch chunk 0 into buffer 0
#pragma unroll
    for (int u = 0; u < 4; u++) {
        cpa16(kdst[0] + u * 16, ksrc + u * 4);
        cpa16(vdst[0] + u * 16, vsrc + u * 4);
    }
    CP_COMMIT();

    float mA[2] = {-3.0e38f, -3.0e38f};
    float mB[2] = {-3.0e38f, -3.0e38f};
    float lA[2] = {0.f, 0.f};
    float lB[2] = {0.f, 0.f};

    float o[2][8][4];
#pragma unroll
    for (int mt = 0; mt < 2; mt++)
#pragma unroll
        for (int nf = 0; nf < 8; nf++)
#pragma unroll
            for (int r = 0; r < 4; r++) o[mt][nf][r] = 0.f;

    for (int kc = 0; kc < 16; kc++) {
        const int buf = kc & 1;
        CP_WAIT0();
        __syncthreads();   // chunk kc staged; all warps done with buf^1

        // prefetch chunk kc+1 into buf^1 (overlapped with compute below)
        if (kc < 15) {
            const int nb = buf ^ 1;
            const float* kn = ksrc + (size_t)(kc + 1) * 32 * 64;
            const float* vn = vsrc + (size_t)(kc + 1) * 32 * 64;
#pragma unroll
            for (int u = 0; u < 4; u++) {
                cpa16(kdst[nb] + u * 16, kn + u * 4);
                cpa16(vdst[nb] + u * 16, vn + u * 4);
            }
            CP_COMMIT();
        }

        // mask registers for this chunk (issued early, covered by S MMAs)
        float2 mk[2][4][2];
#pragma unroll
        for (int mt = 0; mt < 2; mt++) {
            const int rlo = r0 + wrow + mt * 16 + g;
#pragma unroll
            for (int nf = 0; nf < 4; nf++) {
                const int c0 = kc * 32 + nf * 8 + tg * 2;
                mk[mt][nf][0] = *(const float2*)(mask + (size_t)rlo * L_ + c0);
                mk[mt][nf][1] =
                    *(const float2*)(mask + (size_t)(rlo + 8) * L_ + c0);
            }
        }

        const float* Kf = smf + OFF_KB + buf * 32 * KC_STR;
        const float* Vf = smf + OFF_VB + buf * 32 * VC_STR;

        // ---- S = (Q*t1) K^T : 32 q-rows x 32 keys per warp ----
        float s[2][4][4];
#pragma unroll
        for (int mt = 0; mt < 2; mt++)
#pragma unroll
            for (int nf = 0; nf < 4; nf++)
#pragma unroll
                for (int r = 0; r < 4; r++) s[mt][nf][r] = 0.f;

#pragma unroll
        for (int ks = 0; ks < 8; ks++) {
            uint32_t qa[2][4];
#pragma unroll
            for (int mt = 0; mt < 2; mt++) {
                const int rb = wrow + mt * 16;
                qa[mt][0] = Qs[rb + g][ks * 8 + tg];
                qa[mt][1] = Qs[rb + g + 8][ks * 8 + tg];
                qa[mt][2] = Qs[rb + g][ks * 8 + tg + 4];
                qa[mt][3] = Qs[rb + g + 8][ks * 8 + tg + 4];
            }
#pragma unroll
            for (int nf = 0; nf < 4; nf++) {
                const uint32_t b0 =
                    f2tf32(Kf[(nf * 8 + g) * KC_STR + ks * 8 + tg]);
                const uint32_t b1 =
                    f2tf32(Kf[(nf * 8 + g) * KC_STR + ks * 8 + tg + 4]);
                mma_tf32(s[0][nf], qa[0][0], qa[0][1], qa[0][2], qa[0][3],
                         b0, b1);
                mma_tf32(s[1][nf], qa[1][0], qa[1][1], qa[1][2], qa[1][3],
                         b0, b1);
            }
        }

        // ---- epilogue + online softmax + P store, per M-tile ----
#pragma unroll
        for (int mt = 0; mt < 2; mt++) {
#pragma unroll
            for (int nf = 0; nf < 4; nf++) {
                s[mt][nf][0] = (s[mt][nf][0] + t2) * mk[mt][nf][0].x;
                s[mt][nf][1] = (s[mt][nf][1] + t2) * mk[mt][nf][0].y;
                s[mt][nf][2] = (s[mt][nf][2] + t2) * mk[mt][nf][1].x;
                s[mt][nf][3] = (s[mt][nf][3] + t2) * mk[mt][nf][1].y;
            }

            float mx0 = -3.0e38f, mx1 = -3.0e38f;
#pragma unroll
            for (int nf = 0; nf < 4; nf++) {
                mx0 = fmaxf(mx0, fmaxf(s[mt][nf][0], s[mt][nf][1]));
                mx1 = fmaxf(mx1, fmaxf(s[mt][nf][2], s[mt][nf][3]));
            }
            mx0 = fmaxf(mx0, __shfl_xor_sync(0xffffffffu, mx0, 1));
            mx0 = fmaxf(mx0, __shfl_xor_sync(0xffffffffu, mx0, 2));
            mx1 = fmaxf(mx1, __shfl_xor_sync(0xffffffffu, mx1, 1));
            mx1 = fmaxf(mx1, __shfl_xor_sync(0xffffffffu, mx1, 2));

            const float mn0 = fmaxf(mA[mt], mx0);
            const float mn1 = fmaxf(mB[mt], mx1);
            const float al0 = __expf(mA[mt] - mn0);
            const float al1 = __expf(mB[mt] - mn1);

            float sum0 = 0.f, sum1 = 0.f;
#pragma unroll
            for (int nf = 0; nf < 4; nf++) {
                s[mt][nf][0] = __expf(s[mt][nf][0] - mn0);
                s[mt][nf][1] = __expf(s[mt][nf][1] - mn0);
                s[mt][nf][2] = __expf(s[mt][nf][2] - mn1);
                s[mt][nf][3] = __expf(s[mt][nf][3] - mn1);
                sum0 += s[mt][nf][0] + s[mt][nf][1];
                sum1 += s[mt][nf][2] + s[mt][nf][3];
            }
            sum0 += __shfl_xor_sync(0xffffffffu, sum0, 1);
            sum0 += __shfl_xor_sync(0xffffffffu, sum0, 2);
            sum1 += __shfl_xor_sync(0xffffffffu, sum1, 1);
            sum1 += __shfl_xor_sync(0xffffffffu, sum1, 2);

            lA[mt] = lA[mt] * al0 + sum0;  mA[mt] = mn0;
            lB[mt] = lB[mt] * al1 + sum1;  mB[mt] = mn1;

#pragma unroll
            for (int nf = 0; nf < 8; nf++) {
                o[mt][nf][0] *= al0; o[mt][nf][1] *= al0;
                o[mt][nf][2] *= al1; o[mt][nf][3] *= al1;
            }

            const int rb = wrow + mt * 16;
#pragma unroll
            for (int nf = 0; nf < 4; nf++) {
                const int c = nf * 8 + tg * 2;
                uint2 plo, phi;
                plo.x = f2tf32(s[mt][nf][0]); plo.y = f2tf32(s[mt][nf][1]);
                phi.x = f2tf32(s[mt][nf][2]); phi.y = f2tf32(s[mt][nf][3]);
                *(uint2*)&Ps[rb + g][c]     = plo;
                *(uint2*)&Ps[rb + g + 8][c] = phi;
            }
        }
        __syncwarp();   // P STS visible to cross-lane LDS below

        // ---- O += P V : 32 keys, V frags shared by 2 M-tiles ----
#pragma unroll
        for (int ks = 0; ks < 4; ks++) {
            uint32_t pa[2][4];
#pragma unroll
            for (int mt = 0; mt < 2; mt++) {
                const int rb = wrow + mt * 16;
                pa[mt][0] = Ps[rb + g][ks * 8 + tg];
                pa[mt][1] = Ps[rb + g + 8][ks * 8 + tg];
                pa[mt][2] = Ps[rb + g][ks * 8 + tg + 4];
                pa[mt][3] = Ps[rb + g + 8][ks * 8 + tg + 4];
            }
#pragma unroll
            for (int nf = 0; nf < 8; nf++) {
                const uint32_t b0 =
                    f2tf32(Vf[(ks * 8 + tg) * VC_STR + nf * 8 + g]);
                const uint32_t b1 =
                    f2tf32(Vf[(ks * 8 + tg + 4) * VC_STR + nf * 8 + g]);
                mma_tf32(o[0][nf], pa[0][0], pa[0][1], pa[0][2], pa[0][3],
                         b0, b1);
                mma_tf32(o[1][nf], pa[1][0], pa[1][1], pa[1][2], pa[1][3],
                         b0, b1);
            }
        }
    }

    // ---- finalize: *(wh/l), write (bt,h,l,e) ----
    float* obase = Og + headBase;
#pragma unroll
    for (int mt = 0; mt < 2; mt++) {
        const float i0 = wh / lA[mt];
        const float i1 = wh / lB[mt];
        const int rlo = r0 + wrow + mt * 16 + g;
#pragma unroll
        for (int nf = 0; nf < 8; nf++) {
            const int e = nf * 8 + tg * 2;
            float2 v0 = make_float2(o[mt][nf][0] * i0, o[mt][nf][1] * i0);
            float2 v1 = make_float2(o[mt][nf][2] * i1, o[mt][nf][3] * i1);
            *(float2*)(obase + (size_t)rlo * 64 + e)       = v0;
            *(float2*)(obase + (size_t)(rlo + 8) * 64 + e) = v1;
        }
    }
}

// ---------------------------------------------------------------------------
// Head combine: out[bt,l,e] = sum_h O[bt,h,l,e]   (w_h already folded in)
// ---------------------------------------------------------------------------
__global__ __launch_bounds__(256)
void combine_heads(const float* __restrict__ O, float* __restrict__ out) {
    const int idx = blockIdx.x * 256 + threadIdx.x;
    const int btl = idx >> 4;
    const int e   = (idx & 15) * 4;
    const int bt  = btl >> 9;
    const int l   = btl & 511;

    float4 acc = make_float4(0.f, 0.f, 0.f, 0.f);
#pragma unroll
    for (int h = 0; h < H_; h++) {
        const float4 v = *(const float4*)(O +
            (((size_t)(bt * H_ + h)) * L_ + l) * 64 + e);
        acc.x += v.x; acc.y += v.y; acc.z += v.z; acc.w += v.w;
    }
    *(float4*)(out + (size_t)btl * 64 + e) = acc;
}

// ---------------------------------------------------------------------------
extern "C" void kernel_launch(void* const* d_in, const int* in_sizes, int n_in,
                              void* d_out, int out_size) {
    const float* queries = (const float*)d_in[0];
    const float* keys    = (const float*)d_in[1];
    const float* values  = (const float*)d_in[2];
    const float* mask    = (const float*)d_in[3];
    const float* Wq      = (const float*)d_in[4];
    const float* Wk      = (const float*)d_in[5];
    const float* Wv      = (const float*)d_in[6];
    const float* w_head  = (const float*)d_in[7];
    const float* tau     = (const float*)d_in[8];
    const float* delta   = (const float*)d_in[9];
    float* out = (float*)d_out;

    float *qs, *ks, *vs, *os;
    cudaGetSymbolAddress((void**)&qs, g_Q);
    cudaGetSymbolAddress((void**)&ks, g_K);
    cudaGetSymbolAddress((void**)&vs, g_V);
    cudaGetSymbolAddress((void**)&os, g_O);

    cudaFuncSetAttribute(proj3_cp,
                         cudaFuncAttributeMaxDynamicSharedMemorySize,
                         PROJ_SMEM);
    dim3 gp(NDIM / 128, M_TOT / 128, 3);   // (4, 128, 3)
    proj3_cp<<<gp, 256, PROJ_SMEM>>>(queries, keys, values, Wq, Wk, Wv,
                                     qs, ks, vs);

    cudaFuncSetAttribute(attn_tf32,
                         cudaFuncAttributeMaxDynamicSharedMemorySize,
                         ATTN_SMEM);
    dim3 ga(L_ / 128, H_, BT_);            // (4, 8, 32)
    attn_tf32<<<ga, 128, ATTN_SMEM>>>(qs, ks, vs, mask, w_head, tau, delta, os);

    combine_heads<<<1024, 256>>>(os, out);
}